// round 3
// baseline (speedup 1.0000x reference)
#include <cuda_runtime.h>
#include <cuda_bf16.h>
#include <cstdint>

#define N_NODES 50000
#define N_EDGES 800000
#define H 128
#define LN_EPS 1e-5f

// ---------------- scratch (no cudaMalloc allowed) ----------------
__device__ __align__(256) float g_P[(size_t)N_NODES * 256];   // [n][0:128]=x@W1a, [n][128:256]=x@W1b
__device__ __align__(256) float g_accum[(size_t)N_NODES * H]; // residual + segment sum
__device__ __align__(256) __nv_bfloat16 g_Whi[3 * 128 * 128]; // [part][n][k] = hi(W1[part*128+k][n])
__device__ __align__(256) __nv_bfloat16 g_Wlo[3 * 128 * 128];

#define SROW 272  // smem tile row pitch in bytes (136 bf16) -> conflict-free fragment loads

__device__ __forceinline__ void split2(float f, unsigned short& h, unsigned short& l) {
    __nv_bfloat16 hb = __float2bfloat16(f);
    float r = f - __bfloat162float(hb);
    h = __bfloat16_as_ushort(hb);
    l = __bfloat16_as_ushort(__float2bfloat16(r));
}

__device__ __forceinline__ void mma16816(float* c, const uint32_t* a, uint32_t b0, uint32_t b1) {
    asm volatile("mma.sync.aligned.m16n8k16.row.col.f32.bf16.bf16.f32 "
                 "{%0,%1,%2,%3}, {%4,%5,%6,%7}, {%8,%9}, {%0,%1,%2,%3};"
                 : "+f"(c[0]), "+f"(c[1]), "+f"(c[2]), "+f"(c[3])
                 : "r"(a[0]), "r"(a[1]), "r"(a[2]), "r"(a[3]), "r"(b0), "r"(b1));
}

// float4 -> bf16 hi/lo pairs into smem (uint2 = 4 bf16)
__device__ __forceinline__ void store_split4(char* smem, uint32_t offH, uint32_t offL,
                                             int row, int cg, float4 v) {
    unsigned short h0, l0, h1, l1, h2, l2, h3, l3;
    split2(v.x, h0, l0); split2(v.y, h1, l1);
    split2(v.z, h2, l2); split2(v.w, h3, l3);
    uint32_t byte = (uint32_t)row * SROW + (uint32_t)cg * 8;
    *(uint2*)(smem + offH + byte) =
        make_uint2((uint32_t)h0 | ((uint32_t)h1 << 16), (uint32_t)h2 | ((uint32_t)h3 << 16));
    *(uint2*)(smem + offL + byte) =
        make_uint2((uint32_t)l0 | ((uint32_t)l1 << 16), (uint32_t)l2 | ((uint32_t)l3 << 16));
}

// 3-pass split GEMM: C[128,128] += (A_hi+A_lo) @ (B_hi+B_lo) minus lo*lo term.
// Warp (wm, wn) owns 32x64 tile; acc[mt][nt][4] per mma.m16n8k16 C-fragment layout.
__device__ __forceinline__ void gemm3(const char* __restrict__ smem,
                                      uint32_t offAH, uint32_t offAL,
                                      uint32_t offBH, uint32_t offBL,
                                      int wm, int wn, int g, int t4, float acc[2][8][4]) {
#pragma unroll
    for (int pass = 0; pass < 3; pass++) {
        const char* A = smem + ((pass == 2) ? offAL : offAH);
        const char* B = smem + ((pass == 1) ? offBL : offBH);
#pragma unroll
        for (int ks = 0; ks < 8; ks++) {
            int kb = ks * 32 + t4 * 4;  // byte offset of (k0 + t4*2) bf16 pair
            uint32_t a[2][4];
#pragma unroll
            for (int mt = 0; mt < 2; mt++) {
                int row = wm * 32 + mt * 16 + g;
                a[mt][0] = *(const uint32_t*)(A + row * SROW + kb);
                a[mt][1] = *(const uint32_t*)(A + (row + 8) * SROW + kb);
                a[mt][2] = *(const uint32_t*)(A + row * SROW + kb + 16);
                a[mt][3] = *(const uint32_t*)(A + (row + 8) * SROW + kb + 16);
            }
#pragma unroll
            for (int nt = 0; nt < 8; nt++) {
                int n = wn * 64 + nt * 8 + g;
                uint32_t b0 = *(const uint32_t*)(B + n * SROW + kb);
                uint32_t b1 = *(const uint32_t*)(B + n * SROW + kb + 16);
                mma16816(acc[0][nt], a[0], b0, b1);
                mma16816(acc[1][nt], a[1], b0, b1);
            }
        }
    }
}

// ---------------- K_w: split weights into bf16 hi/lo, transposed to [part][n][k] ----------------
__global__ __launch_bounds__(256) void splitw_kernel(const float* __restrict__ W1) {
    int i = blockIdx.x * 256 + threadIdx.x;
    if (i >= 3 * 128 * 128) return;
    int part = i >> 14, nk = i & 16383, n = nk >> 7, k = nk & 127;
    float w = W1[(size_t)(part * 128 + k) * H + n];
    unsigned short h, l;
    split2(w, h, l);
    g_Whi[i] = __ushort_as_bfloat16(h);
    g_Wlo[i] = __ushort_as_bfloat16(l);
}

// ---------------- K0: accum = x ----------------
__global__ __launch_bounds__(256) void init_accum_kernel(const float* __restrict__ x) {
    size_t i = (size_t)blockIdx.x * blockDim.x + threadIdx.x;
    ((float4*)g_accum)[i] = ((const float4*)x)[i];
}

// ---------------- K1: node projections P = x @ [W1a | W1b] ----------------
#define N_A_HI 0
#define N_A_LO (N_A_HI + 34816)
#define N_B_HI (N_A_LO + 34816)
#define N_B_LO (N_B_HI + 34816)
#define NODE_SMEM (N_B_LO + 34816)

__global__ __launch_bounds__(256, 1) void node_proj_kernel(const float* __restrict__ x) {
    extern __shared__ __align__(16) char smem[];
    const int tid = threadIdx.x, wid = tid >> 5, lane = tid & 31;
    const int g = lane >> 2, t4 = lane & 3, wm = wid & 3, wn = wid >> 2;
    const int part = blockIdx.y;  // 0 -> W1a, 1 -> W1b
    const int n0 = blockIdx.x * 128;

    // B = W part (bf16 [n][k], pre-split)
    const uint2* wh = (const uint2*)(g_Whi + part * 16384);
    const uint2* wl = (const uint2*)(g_Wlo + part * 16384);
#pragma unroll
    for (int i = tid; i < 4096; i += 256) {
        uint32_t byte = (uint32_t)(i >> 5) * SROW + (uint32_t)(i & 31) * 8;
        *(uint2*)(smem + N_B_HI + byte) = wh[i];
        *(uint2*)(smem + N_B_LO + byte) = wl[i];
    }
    // A = x tile (rows past N_NODES -> zero)
    const float4* x4 = (const float4*)x;
#pragma unroll
    for (int i = tid; i < 4096; i += 256) {
        int row = i >> 5, cg = i & 31;
        int n = n0 + row;
        float4 v = (n < N_NODES) ? x4[(size_t)n * 32 + cg] : make_float4(0.f, 0.f, 0.f, 0.f);
        store_split4(smem, N_A_HI, N_A_LO, row, cg, v);
    }
    __syncthreads();

    float acc[2][8][4];
#pragma unroll
    for (int mt = 0; mt < 2; mt++)
#pragma unroll
        for (int nt = 0; nt < 8; nt++)
#pragma unroll
            for (int q = 0; q < 4; q++) acc[mt][nt][q] = 0.f;

    gemm3(smem, N_A_HI, N_A_LO, N_B_HI, N_B_LO, wm, wn, g, t4, acc);

    // epilogue: store to g_P[n][part*128 + c]
#pragma unroll
    for (int mt = 0; mt < 2; mt++) {
#pragma unroll
        for (int rh = 0; rh < 2; rh++) {
            int row = wm * 32 + mt * 16 + rh * 8 + g;
            int n = n0 + row;
            if (n >= N_NODES) continue;
            float* dst = g_P + (size_t)n * 256 + part * 128;
#pragma unroll
            for (int nt = 0; nt < 8; nt++) {
                int c = wn * 64 + nt * 8 + t4 * 2;
                *(float2*)(dst + c) = make_float2(acc[mt][nt][rh * 2 + 0], acc[mt][nt][rh * 2 + 1]);
            }
        }
    }
}

// ---------------- K2: edge kernel ----------------
#define E_IDX_S 0
#define E_IDX_R 512
#define E_B1    1024
#define E_A_HI  1536
#define E_A_LO  (E_A_HI + 34816)
#define E_B_HI  (E_A_LO + 34816)
#define E_B_LO  (E_B_HI + 34816)
#define EDGE_SMEM (E_B_LO + 34816)

__global__ __launch_bounds__(256, 1) void edge_kernel(const float* __restrict__ edge_feat,
                                                      const int* __restrict__ senders,
                                                      const int* __restrict__ receivers,
                                                      const float* __restrict__ b1) {
    extern __shared__ __align__(16) char smem[];
    const int tid = threadIdx.x, wid = tid >> 5, lane = tid & 31;
    const int g = lane >> 2, t4 = lane & 3, wm = wid & 3, wn = wid >> 2;
    const size_t e0 = (size_t)blockIdx.x * 128;

    if (tid < 128) {
        ((int*)(smem + E_IDX_S))[tid] = senders[e0 + tid];
        ((int*)(smem + E_IDX_R))[tid] = receivers[e0 + tid];
        ((float*)(smem + E_B1))[tid] = b1[tid];
    }
    // B = W1c (part 2)
    const uint2* wh = (const uint2*)(g_Whi + 2 * 16384);
    const uint2* wl = (const uint2*)(g_Wlo + 2 * 16384);
#pragma unroll
    for (int i = tid; i < 4096; i += 256) {
        uint32_t byte = (uint32_t)(i >> 5) * SROW + (uint32_t)(i & 31) * 8;
        *(uint2*)(smem + E_B_HI + byte) = wh[i];
        *(uint2*)(smem + E_B_LO + byte) = wl[i];
    }
    // A = edge_feat tile
    const float4* a4 = (const float4*)(edge_feat + e0 * H);
#pragma unroll
    for (int i = tid; i < 4096; i += 256) {
        store_split4(smem, E_A_HI, E_A_LO, i >> 5, i & 31, a4[i]);
    }
    __syncthreads();

    float acc[2][8][4];
#pragma unroll
    for (int mt = 0; mt < 2; mt++)
#pragma unroll
        for (int nt = 0; nt < 8; nt++)
#pragma unroll
            for (int q = 0; q < 4; q++) acc[mt][nt][q] = 0.f;

    gemm3(smem, E_A_HI, E_A_LO, E_B_HI, E_B_LO, wm, wn, g, t4, acc);

    // epilogue: msg = relu(D + P_s[0:128] + P_r[128:256] + b1); red.add into accum[r]
    const float* b1s = (const float*)(smem + E_B1);
    const int* ss = (const int*)(smem + E_IDX_S);
    const int* rr = (const int*)(smem + E_IDX_R);
#pragma unroll
    for (int mt = 0; mt < 2; mt++) {
#pragma unroll
        for (int rh = 0; rh < 2; rh++) {
            int row = wm * 32 + mt * 16 + rh * 8 + g;
            int s = ss[row];
            int r = rr[row];
            const float* Ps = g_P + (size_t)s * 256;
            const float* Pr = g_P + (size_t)r * 256 + 128;
            float* ac = g_accum + (size_t)r * H;
#pragma unroll
            for (int nt = 0; nt < 8; nt++) {
                int c = wn * 64 + nt * 8 + t4 * 2;
                float2 ps = *(const float2*)(Ps + c);
                float2 pr = *(const float2*)(Pr + c);
                float v0 = fmaxf(acc[mt][nt][rh * 2 + 0] + ps.x + pr.x + b1s[c], 0.f);
                float v1 = fmaxf(acc[mt][nt][rh * 2 + 1] + ps.y + pr.y + b1s[c + 1], 0.f);
                asm volatile("red.global.add.v2.f32 [%0], {%1,%2};"
                             :: "l"(ac + c), "f"(v0), "f"(v1) : "memory");
            }
        }
    }
}

// ---------------- K3: layernorm ----------------
__global__ __launch_bounds__(256) void ln_kernel(const float* __restrict__ gamma,
                                                 const float* __restrict__ beta,
                                                 float* __restrict__ out) {
    const int wid = threadIdx.x >> 5, lid = threadIdx.x & 31;
    const int n = blockIdx.x * 8 + wid;
    if (n >= N_NODES) return;
    float4 v = ((const float4*)(g_accum + (size_t)n * H))[lid];
    float s = v.x + v.y + v.z + v.w;
#pragma unroll
    for (int o = 16; o > 0; o >>= 1) s += __shfl_xor_sync(0xFFFFFFFFu, s, o);
    float mu = s * (1.0f / H);
    float dx = v.x - mu, dy = v.y - mu, dz = v.z - mu, dw = v.w - mu;
    float ss = dx * dx + dy * dy + dz * dz + dw * dw;
#pragma unroll
    for (int o = 16; o > 0; o >>= 1) ss += __shfl_xor_sync(0xFFFFFFFFu, ss, o);
    float rs = rsqrtf(ss * (1.0f / H) + LN_EPS);
    float4 gm = ((const float4*)gamma)[lid];
    float4 b = ((const float4*)beta)[lid];
    float4 o4 = make_float4(gm.x * dx * rs + b.x, gm.y * dy * rs + b.y,
                            gm.z * dz * rs + b.z, gm.w * dw * rs + b.w);
    ((float4*)(out + (size_t)n * H))[lid] = o4;
}

// ---------------- launch ----------------
extern "C" void kernel_launch(void* const* d_in, const int* in_sizes, int n_in,
                              void* d_out, int out_size) {
    const float* x         = (const float*)d_in[0];
    const int*   senders   = (const int*)d_in[1];
    const int*   receivers = (const int*)d_in[2];
    const float* edge_feat = (const float*)d_in[3];
    const float* W1        = (const float*)d_in[4];
    const float* b1        = (const float*)d_in[5];
    const float* gamma     = (const float*)d_in[6];
    const float* beta      = (const float*)d_in[7];
    float* out = (float*)d_out;

    cudaFuncSetAttribute(node_proj_kernel, cudaFuncAttributeMaxDynamicSharedMemorySize, NODE_SMEM);
    cudaFuncSetAttribute(edge_kernel, cudaFuncAttributeMaxDynamicSharedMemorySize, EDGE_SMEM);

    splitw_kernel<<<192, 256>>>(W1);
    init_accum_kernel<<<(N_NODES * H / 4) / 256, 256>>>(x);
    node_proj_kernel<<<dim3((N_NODES + 127) / 128, 2), 256, NODE_SMEM>>>(x);
    edge_kernel<<<N_EDGES / 128, 256, EDGE_SMEM>>>(edge_feat, senders, receivers, b1);
    ln_kernel<<<(N_NODES + 7) / 8, 256>>>(gamma, beta, out);
}

// round 4
// speedup vs baseline: 1.3015x; 1.3015x over previous
#include <cuda_runtime.h>
#include <cuda_bf16.h>
#include <cstdint>

#define N_NODES 50000
#define N_EDGES 800000
#define H 128
#define LN_EPS 1e-5f
#define N_TILES (N_EDGES / 128)
#define EDGE_GRID 152

// ---------------- scratch (no cudaMalloc allowed) ----------------
__device__ __align__(256) float g_P[(size_t)N_NODES * 256];   // [n][0:128]=x@W1a, [n][128:256]=x@W1b
__device__ __align__(256) float g_accum[(size_t)N_NODES * H]; // residual + segment sum
__device__ __align__(256) __nv_bfloat16 g_Whi[3 * 128 * 128]; // [part][n][k] = hi(W1[part*128+k][n])
__device__ __align__(256) __nv_bfloat16 g_Wlo[3 * 128 * 128];

#define SROW 272  // smem tile row pitch in bytes (136 bf16) -> conflict-free fragment loads

__device__ __forceinline__ void split2(float f, unsigned short& h, unsigned short& l) {
    __nv_bfloat16 hb = __float2bfloat16(f);
    float r = f - __bfloat162float(hb);
    h = __bfloat16_as_ushort(hb);
    l = __bfloat16_as_ushort(__float2bfloat16(r));
}

__device__ __forceinline__ void mma16816(float* c, const uint32_t* a, uint32_t b0, uint32_t b1) {
    asm volatile("mma.sync.aligned.m16n8k16.row.col.f32.bf16.bf16.f32 "
                 "{%0,%1,%2,%3}, {%4,%5,%6,%7}, {%8,%9}, {%0,%1,%2,%3};"
                 : "+f"(c[0]), "+f"(c[1]), "+f"(c[2]), "+f"(c[3])
                 : "r"(a[0]), "r"(a[1]), "r"(a[2]), "r"(a[3]), "r"(b0), "r"(b1));
}

__device__ __forceinline__ void cp16(uint32_t dst, const void* src) {
    asm volatile("cp.async.cg.shared.global [%0], [%1], 16;" :: "r"(dst), "l"(src) : "memory");
}
#define CP_COMMIT() asm volatile("cp.async.commit_group;" ::: "memory")
#define CP_WAIT0()  asm volatile("cp.async.wait_group 0;" ::: "memory")

// float4 -> bf16 hi/lo pairs into smem (uint2 = 4 bf16)
__device__ __forceinline__ void store_split4(char* smem, uint32_t offH, uint32_t offL,
                                             int row, int cg, float4 v) {
    unsigned short h0, l0, h1, l1, h2, l2, h3, l3;
    split2(v.x, h0, l0); split2(v.y, h1, l1);
    split2(v.z, h2, l2); split2(v.w, h3, l3);
    uint32_t byte = (uint32_t)row * SROW + (uint32_t)cg * 8;
    *(uint2*)(smem + offH + byte) =
        make_uint2((uint32_t)h0 | ((uint32_t)h1 << 16), (uint32_t)h2 | ((uint32_t)h3 << 16));
    *(uint2*)(smem + offL + byte) =
        make_uint2((uint32_t)l0 | ((uint32_t)l1 << 16), (uint32_t)l2 | ((uint32_t)l3 << 16));
}

// ============ 3-pass split GEMM (32x64 warp tiles, 256-thr kernels) ============
__device__ __forceinline__ void gemm3(const char* __restrict__ smem,
                                      uint32_t offAH, uint32_t offAL,
                                      uint32_t offBH, uint32_t offBL,
                                      int wm, int wn, int g, int t4, float acc[2][8][4]) {
#pragma unroll
    for (int pass = 0; pass < 3; pass++) {
        const char* A = smem + ((pass == 2) ? offAL : offAH);
        const char* B = smem + ((pass == 1) ? offBL : offBH);
#pragma unroll
        for (int ks = 0; ks < 8; ks++) {
            int kb = ks * 32 + t4 * 4;
            uint32_t a[2][4];
#pragma unroll
            for (int mt = 0; mt < 2; mt++) {
                int row = wm * 32 + mt * 16 + g;
                a[mt][0] = *(const uint32_t*)(A + row * SROW + kb);
                a[mt][1] = *(const uint32_t*)(A + (row + 8) * SROW + kb);
                a[mt][2] = *(const uint32_t*)(A + row * SROW + kb + 16);
                a[mt][3] = *(const uint32_t*)(A + (row + 8) * SROW + kb + 16);
            }
#pragma unroll
            for (int nt = 0; nt < 8; nt++) {
                int n = wn * 64 + nt * 8 + g;
                uint32_t b0 = *(const uint32_t*)(B + n * SROW + kb);
                uint32_t b1 = *(const uint32_t*)(B + n * SROW + kb + 16);
                mma16816(acc[0][nt], a[0], b0, b1);
                mma16816(acc[1][nt], a[1], b0, b1);
            }
        }
    }
}

// ---------------- K_w: split weights into bf16 hi/lo, transposed to [part][n][k] ----------------
__global__ __launch_bounds__(256) void splitw_kernel(const float* __restrict__ W1) {
    int i = blockIdx.x * 256 + threadIdx.x;
    if (i >= 3 * 128 * 128) return;
    int part = i >> 14, nk = i & 16383, n = nk >> 7, k = nk & 127;
    float w = W1[(size_t)(part * 128 + k) * H + n];
    unsigned short h, l;
    split2(w, h, l);
    g_Whi[i] = __ushort_as_bfloat16(h);
    g_Wlo[i] = __ushort_as_bfloat16(l);
}

// ---------------- K0: accum = x ----------------
__global__ __launch_bounds__(256) void init_accum_kernel(const float* __restrict__ x) {
    size_t i = (size_t)blockIdx.x * blockDim.x + threadIdx.x;
    ((float4*)g_accum)[i] = ((const float4*)x)[i];
}

// ---------------- K1: node projections P = x @ [W1a | W1b] ----------------
#define N_A_HI 0
#define N_A_LO (N_A_HI + 34816)
#define N_B_HI (N_A_LO + 34816)
#define N_B_LO (N_B_HI + 34816)
#define NODE_SMEM (N_B_LO + 34816)

__global__ __launch_bounds__(256, 1) void node_proj_kernel(const float* __restrict__ x) {
    extern __shared__ __align__(16) char smem[];
    const int tid = threadIdx.x, wid = tid >> 5, lane = tid & 31;
    const int g = lane >> 2, t4 = lane & 3, wm = wid & 3, wn = wid >> 2;
    const int part = blockIdx.y;
    const int n0 = blockIdx.x * 128;

    const uint2* wh = (const uint2*)(g_Whi + part * 16384);
    const uint2* wl = (const uint2*)(g_Wlo + part * 16384);
#pragma unroll
    for (int i = tid; i < 4096; i += 256) {
        uint32_t byte = (uint32_t)(i >> 5) * SROW + (uint32_t)(i & 31) * 8;
        *(uint2*)(smem + N_B_HI + byte) = wh[i];
        *(uint2*)(smem + N_B_LO + byte) = wl[i];
    }
    const float4* x4 = (const float4*)x;
#pragma unroll
    for (int i = tid; i < 4096; i += 256) {
        int row = i >> 5, cg = i & 31;
        int n = n0 + row;
        float4 v = (n < N_NODES) ? x4[(size_t)n * 32 + cg] : make_float4(0.f, 0.f, 0.f, 0.f);
        store_split4(smem, N_A_HI, N_A_LO, row, cg, v);
    }
    __syncthreads();

    float acc[2][8][4];
#pragma unroll
    for (int mt = 0; mt < 2; mt++)
#pragma unroll
        for (int nt = 0; nt < 8; nt++)
#pragma unroll
            for (int q = 0; q < 4; q++) acc[mt][nt][q] = 0.f;

    gemm3(smem, N_A_HI, N_A_LO, N_B_HI, N_B_LO, wm, wn, g, t4, acc);

#pragma unroll
    for (int mt = 0; mt < 2; mt++) {
#pragma unroll
        for (int rh = 0; rh < 2; rh++) {
            int row = wm * 32 + mt * 16 + rh * 8 + g;
            int n = n0 + row;
            if (n >= N_NODES) continue;
            float* dst = g_P + (size_t)n * 256 + part * 128;
#pragma unroll
            for (int nt = 0; nt < 8; nt++) {
                int c = wn * 64 + nt * 8 + t4 * 2;
                *(float2*)(dst + c) = make_float2(acc[mt][nt][rh * 2 + 0], acc[mt][nt][rh * 2 + 1]);
            }
        }
    }
}

// ============ K2: persistent pipelined edge kernel (512 thr, 32x32 warp tiles) ============
#define E_B1   0
#define E_IDX  512                    // 2 x 1024 B (double-buffered s[128],r[128])
#define E_RAW  (E_IDX + 2048)         // 128x128 f32 = 65536
#define E_B_HI (E_RAW + 65536)
#define E_B_LO (E_B_HI + 34816)
#define E_A_HI (E_B_LO + 34816)
#define E_A_LO (E_A_HI + 34816)
#define EDGE_SMEM (E_A_LO + 34816)    // 207360 B

__global__ __launch_bounds__(512, 1) void edge_kernel(const float* __restrict__ edge_feat,
                                                      const int* __restrict__ senders,
                                                      const int* __restrict__ receivers,
                                                      const float* __restrict__ b1) {
    extern __shared__ __align__(16) char smem[];
    uint32_t sb;
    asm("{ .reg .u64 t; cvta.to.shared.u64 t, %1; cvt.u32.u64 %0, t; }" : "=r"(sb) : "l"(smem));
    const int tid = threadIdx.x, wid = tid >> 5, lane = tid & 31;
    const int g = lane >> 2, t4 = lane & 3, wm = wid & 3, wn = wid >> 2;

    // ---- one-time: weights (part 2) + b1 into smem ----
    {
        const uint2* wh = (const uint2*)(g_Whi + 2 * 16384);
        const uint2* wl = (const uint2*)(g_Wlo + 2 * 16384);
#pragma unroll
        for (int i = tid; i < 4096; i += 512) {
            uint32_t byte = (uint32_t)(i >> 5) * SROW + (uint32_t)(i & 31) * 8;
            *(uint2*)(smem + E_B_HI + byte) = wh[i];
            *(uint2*)(smem + E_B_LO + byte) = wl[i];
        }
        if (tid < 128) ((float*)(smem + E_B1))[tid] = b1[tid];
    }

    // ---- prefetch helper: tile t -> RAW + idx buffer p ----
    auto prefetch = [&](int t, int p) {
        if (t < N_TILES) {
            size_t e0 = (size_t)t * 128;
            const char* src = (const char*)(edge_feat + e0 * H);
#pragma unroll
            for (int j = 0; j < 8; j++) {
                int i = tid + j * 512;
                cp16(sb + E_RAW + i * 16, src + (size_t)i * 16);
            }
            if (tid < 32)
                cp16(sb + E_IDX + p * 1024 + tid * 16, (const char*)(senders + e0) + tid * 16);
            else if (tid < 64)
                cp16(sb + E_IDX + p * 1024 + 512 + (tid - 32) * 16,
                     (const char*)(receivers + e0) + (tid - 32) * 16);
        }
        CP_COMMIT();
    };

    const int stride = gridDim.x;
    int it = 0;
    prefetch(blockIdx.x, 0);

    for (int t = blockIdx.x; t < N_TILES; t += stride, it++) {
        CP_WAIT0();
        __syncthreads();   // RAW+idx ready; prior tile's gemm/epilogue done in all warps

        // ---- convert RAW f32 -> A_HI/A_LO bf16 split ----
#pragma unroll
        for (int i = tid; i < 8192; i += 512) {
            int row = i >> 6, c2 = i & 63;
            float2 v = *(const float2*)(smem + E_RAW + (size_t)i * 8);
            unsigned short h0, l0, h1, l1;
            split2(v.x, h0, l0); split2(v.y, h1, l1);
            uint32_t byte = (uint32_t)row * SROW + (uint32_t)c2 * 4;
            *(uint32_t*)(smem + E_A_HI + byte) = (uint32_t)h0 | ((uint32_t)h1 << 16);
            *(uint32_t*)(smem + E_A_LO + byte) = (uint32_t)l0 | ((uint32_t)l1 << 16);
        }
        __syncthreads();   // split visible; RAW free for next prefetch

        prefetch(t + stride, (it + 1) & 1);

        // ---- GEMM: 32x32 warp tile, unified per-ks fragment loads, 3 passes fused ----
        float acc[2][4][4];
#pragma unroll
        for (int mt = 0; mt < 2; mt++)
#pragma unroll
            for (int nt = 0; nt < 4; nt++)
#pragma unroll
                for (int q = 0; q < 4; q++) acc[mt][nt][q] = 0.f;

        const char* AH = smem + E_A_HI;
        const char* AL = smem + E_A_LO;
        const char* BH = smem + E_B_HI;
        const char* BL = smem + E_B_LO;
#pragma unroll
        for (int ks = 0; ks < 8; ks++) {
            const int kb = ks * 32 + t4 * 4;
            uint32_t ah[2][4], al[2][4];
#pragma unroll
            for (int mt = 0; mt < 2; mt++) {
                int row = wm * 32 + mt * 16 + g;
                ah[mt][0] = *(const uint32_t*)(AH + row * SROW + kb);
                ah[mt][1] = *(const uint32_t*)(AH + (row + 8) * SROW + kb);
                ah[mt][2] = *(const uint32_t*)(AH + row * SROW + kb + 16);
                ah[mt][3] = *(const uint32_t*)(AH + (row + 8) * SROW + kb + 16);
                al[mt][0] = *(const uint32_t*)(AL + row * SROW + kb);
                al[mt][1] = *(const uint32_t*)(AL + (row + 8) * SROW + kb);
                al[mt][2] = *(const uint32_t*)(AL + row * SROW + kb + 16);
                al[mt][3] = *(const uint32_t*)(AL + (row + 8) * SROW + kb + 16);
            }
#pragma unroll
            for (int nt = 0; nt < 4; nt++) {
                int n = wn * 32 + nt * 8 + g;
                uint32_t bh0 = *(const uint32_t*)(BH + n * SROW + kb);
                uint32_t bh1 = *(const uint32_t*)(BH + n * SROW + kb + 16);
                uint32_t bl0 = *(const uint32_t*)(BL + n * SROW + kb);
                uint32_t bl1 = *(const uint32_t*)(BL + n * SROW + kb + 16);
#pragma unroll
                for (int mt = 0; mt < 2; mt++) {
                    mma16816(acc[mt][nt], ah[mt], bh0, bh1);
                    mma16816(acc[mt][nt], ah[mt], bl0, bl1);
                    mma16816(acc[mt][nt], al[mt], bh0, bh1);
                }
            }
        }

        // ---- epilogue: relu(D + P_s + P_r + b1) -> red.add accum[r] ----
        const int* ss = (const int*)(smem + E_IDX + (it & 1) * 1024);
        const int* rr = ss + 128;
        const float* b1s = (const float*)(smem + E_B1);
#pragma unroll
        for (int mt = 0; mt < 2; mt++) {
#pragma unroll
            for (int rh = 0; rh < 2; rh++) {
                int row = wm * 32 + mt * 16 + rh * 8 + g;
                int s = ss[row];
                int r = rr[row];
                const float* Ps = g_P + (size_t)s * 256;
                const float* Pr = g_P + (size_t)r * 256 + 128;
                float* ac = g_accum + (size_t)r * H;
#pragma unroll
                for (int nt = 0; nt < 4; nt++) {
                    int c = wn * 32 + nt * 8 + t4 * 2;
                    float2 ps = *(const float2*)(Ps + c);
                    float2 pr = *(const float2*)(Pr + c);
                    float2 bb = *(const float2*)(b1s + c);
                    float v0 = fmaxf(acc[mt][nt][rh * 2 + 0] + ps.x + pr.x + bb.x, 0.f);
                    float v1 = fmaxf(acc[mt][nt][rh * 2 + 1] + ps.y + pr.y + bb.y, 0.f);
                    asm volatile("red.global.add.v2.f32 [%0], {%1,%2};"
                                 :: "l"(ac + c), "f"(v0), "f"(v1) : "memory");
                }
            }
        }
    }
}

// ---------------- K3: layernorm ----------------
__global__ __launch_bounds__(256) void ln_kernel(const float* __restrict__ gamma,
                                                 const float* __restrict__ beta,
                                                 float* __restrict__ out) {
    const int wid = threadIdx.x >> 5, lid = threadIdx.x & 31;
    const int n = blockIdx.x * 8 + wid;
    if (n >= N_NODES) return;
    float4 v = ((const float4*)(g_accum + (size_t)n * H))[lid];
    float s = v.x + v.y + v.z + v.w;
#pragma unroll
    for (int o = 16; o > 0; o >>= 1) s += __shfl_xor_sync(0xFFFFFFFFu, s, o);
    float mu = s * (1.0f / H);
    float dx = v.x - mu, dy = v.y - mu, dz = v.z - mu, dw = v.w - mu;
    float ss = dx * dx + dy * dy + dz * dz + dw * dw;
#pragma unroll
    for (int o = 16; o > 0; o >>= 1) ss += __shfl_xor_sync(0xFFFFFFFFu, ss, o);
    float rs = rsqrtf(ss * (1.0f / H) + LN_EPS);
    float4 gm = ((const float4*)gamma)[lid];
    float4 b = ((const float4*)beta)[lid];
    float4 o4 = make_float4(gm.x * dx * rs + b.x, gm.y * dy * rs + b.y,
                            gm.z * dz * rs + b.z, gm.w * dw * rs + b.w);
    ((float4*)(out + (size_t)n * H))[lid] = o4;
}

// ---------------- launch ----------------
extern "C" void kernel_launch(void* const* d_in, const int* in_sizes, int n_in,
                              void* d_out, int out_size) {
    const float* x         = (const float*)d_in[0];
    const int*   senders   = (const int*)d_in[1];
    const int*   receivers = (const int*)d_in[2];
    const float* edge_feat = (const float*)d_in[3];
    const float* W1        = (const float*)d_in[4];
    const float* b1        = (const float*)d_in[5];
    const float* gamma     = (const float*)d_in[6];
    const float* beta      = (const float*)d_in[7];
    float* out = (float*)d_out;

    cudaFuncSetAttribute(node_proj_kernel, cudaFuncAttributeMaxDynamicSharedMemorySize, NODE_SMEM);
    cudaFuncSetAttribute(edge_kernel, cudaFuncAttributeMaxDynamicSharedMemorySize, EDGE_SMEM);

    splitw_kernel<<<192, 256>>>(W1);
    init_accum_kernel<<<(N_NODES * H / 4) / 256, 256>>>(x);
    node_proj_kernel<<<dim3((N_NODES + 127) / 128, 2), 256, NODE_SMEM>>>(x);
    edge_kernel<<<EDGE_GRID, 512, EDGE_SMEM>>>(edge_feat, senders, receivers, b1);
    ln_kernel<<<(N_NODES + 7) / 8, 256>>>(gamma, beta, out);
}

// round 5
// speedup vs baseline: 1.4448x; 1.1101x over previous
#include <cuda_runtime.h>
#include <cuda_bf16.h>
#include <cstdint>

#define N_NODES 50000
#define N_EDGES 800000
#define H 128
#define LN_EPS 1e-5f
#define TILE_M 64
#define N_TILES (N_EDGES / TILE_M)
#define EDGE_GRID 304

// ---------------- scratch (no cudaMalloc allowed) ----------------
__device__ __align__(256) float g_P[(size_t)N_NODES * 256];   // [n][0:128]=x@W1a, [n][128:256]=x@W1b
__device__ __align__(256) float g_accum[(size_t)N_NODES * H]; // residual + segment sum
__device__ __align__(256) __nv_bfloat16 g_Whi[3 * 128 * 128]; // [part][n][k] (node kernel layout)
__device__ __align__(256) __nv_bfloat16 g_Wlo[3 * 128 * 128];
__device__ __align__(256) uint2 g_Bpack[2][8][128][4];        // [hi/lo][ks][n][t4] = {b0,b1} frag regs

#define SROW 272  // node-kernel smem pitch (bf16 tiles)
#define RROW 528  // edge-kernel raw fp32 tile pitch (<=2-way conflicts on LDS.64)

__device__ __forceinline__ void split2(float f, unsigned short& h, unsigned short& l) {
    __nv_bfloat16 hb = __float2bfloat16(f);
    float r = f - __bfloat162float(hb);
    h = __bfloat16_as_ushort(hb);
    l = __bfloat16_as_ushort(__float2bfloat16(r));
}

__device__ __forceinline__ void mma16816(float* c, const uint32_t* a, uint32_t b0, uint32_t b1) {
    asm volatile("mma.sync.aligned.m16n8k16.row.col.f32.bf16.bf16.f32 "
                 "{%0,%1,%2,%3}, {%4,%5,%6,%7}, {%8,%9}, {%0,%1,%2,%3};"
                 : "+f"(c[0]), "+f"(c[1]), "+f"(c[2]), "+f"(c[3])
                 : "r"(a[0]), "r"(a[1]), "r"(a[2]), "r"(a[3]), "r"(b0), "r"(b1));
}

__device__ __forceinline__ void cp16(uint32_t dst, const void* src) {
    asm volatile("cp.async.cg.shared.global [%0], [%1], 16;" :: "r"(dst), "l"(src) : "memory");
}
#define CP_COMMIT() asm volatile("cp.async.commit_group;" ::: "memory")
#define CP_WAIT0()  asm volatile("cp.async.wait_group 0;" ::: "memory")

// float4 -> bf16 hi/lo pairs into smem (uint2 = 4 bf16) -- node kernel
__device__ __forceinline__ void store_split4(char* smem, uint32_t offH, uint32_t offL,
                                             int row, int cg, float4 v) {
    unsigned short h0, l0, h1, l1, h2, l2, h3, l3;
    split2(v.x, h0, l0); split2(v.y, h1, l1);
    split2(v.z, h2, l2); split2(v.w, h3, l3);
    uint32_t byte = (uint32_t)row * SROW + (uint32_t)cg * 8;
    *(uint2*)(smem + offH + byte) =
        make_uint2((uint32_t)h0 | ((uint32_t)h1 << 16), (uint32_t)h2 | ((uint32_t)h3 << 16));
    *(uint2*)(smem + offL + byte) =
        make_uint2((uint32_t)l0 | ((uint32_t)l1 << 16), (uint32_t)l2 | ((uint32_t)l3 << 16));
}

// ---------------- K_w: split weights (node layout) ----------------
__global__ __launch_bounds__(256) void splitw_kernel(const float* __restrict__ W1) {
    int i = blockIdx.x * 256 + threadIdx.x;
    if (i >= 3 * 128 * 128) return;
    int part = i >> 14, nk = i & 16383, n = nk >> 7, k = nk & 127;
    float w = W1[(size_t)(part * 128 + k) * H + n];
    unsigned short h, l;
    split2(w, h, l);
    g_Whi[i] = __ushort_as_bfloat16(h);
    g_Wlo[i] = __ushort_as_bfloat16(l);
}

// ---------------- K_w2: pack W1c fragment-major for edge kernel ----------------
__global__ __launch_bounds__(256) void packw_kernel(const float* __restrict__ W1) {
    int i = blockIdx.x * 256 + threadIdx.x;  // 4096 = 8 ks * 128 n * 4 t4
    if (i >= 4096) return;
    int ks = i >> 9, n = (i >> 2) & 127, t4 = i & 3;
    int k0 = ks * 16 + t4 * 2;
    unsigned short h[4], l[4];
    split2(W1[(size_t)(256 + k0 + 0) * H + n], h[0], l[0]);
    split2(W1[(size_t)(256 + k0 + 1) * H + n], h[1], l[1]);
    split2(W1[(size_t)(256 + k0 + 8) * H + n], h[2], l[2]);
    split2(W1[(size_t)(256 + k0 + 9) * H + n], h[3], l[3]);
    g_Bpack[0][ks][n][t4] =
        make_uint2((uint32_t)h[0] | ((uint32_t)h[1] << 16), (uint32_t)h[2] | ((uint32_t)h[3] << 16));
    g_Bpack[1][ks][n][t4] =
        make_uint2((uint32_t)l[0] | ((uint32_t)l[1] << 16), (uint32_t)l[2] | ((uint32_t)l[3] << 16));
}

// ---------------- K0: accum = x ----------------
__global__ __launch_bounds__(256) void init_accum_kernel(const float* __restrict__ x) {
    size_t i = (size_t)blockIdx.x * blockDim.x + threadIdx.x;
    ((float4*)g_accum)[i] = ((const float4*)x)[i];
}

// ---------------- K1: node projections P = x @ [W1a | W1b] (unchanged) ----------------
#define N_A_HI 0
#define N_A_LO (N_A_HI + 34816)
#define N_B_HI (N_A_LO + 34816)
#define N_B_LO (N_B_HI + 34816)
#define NODE_SMEM (N_B_LO + 34816)

__global__ __launch_bounds__(256, 1) void node_proj_kernel(const float* __restrict__ x) {
    extern __shared__ __align__(16) char smem[];
    const int tid = threadIdx.x, wid = tid >> 5, lane = tid & 31;
    const int g = lane >> 2, t4 = lane & 3, wm = wid & 3, wn = wid >> 2;
    const int part = blockIdx.y;
    const int n0 = blockIdx.x * 128;

    const uint2* wh = (const uint2*)(g_Whi + part * 16384);
    const uint2* wl = (const uint2*)(g_Wlo + part * 16384);
#pragma unroll
    for (int i = tid; i < 4096; i += 256) {
        uint32_t byte = (uint32_t)(i >> 5) * SROW + (uint32_t)(i & 31) * 8;
        *(uint2*)(smem + N_B_HI + byte) = wh[i];
        *(uint2*)(smem + N_B_LO + byte) = wl[i];
    }
    const float4* x4 = (const float4*)x;
#pragma unroll
    for (int i = tid; i < 4096; i += 256) {
        int row = i >> 5, cg = i & 31;
        int n = n0 + row;
        float4 v = (n < N_NODES) ? x4[(size_t)n * 32 + cg] : make_float4(0.f, 0.f, 0.f, 0.f);
        store_split4(smem, N_A_HI, N_A_LO, row, cg, v);
    }
    __syncthreads();

    float acc[2][8][4];
#pragma unroll
    for (int mt = 0; mt < 2; mt++)
#pragma unroll
        for (int nt = 0; nt < 8; nt++)
#pragma unroll
            for (int q = 0; q < 4; q++) acc[mt][nt][q] = 0.f;

#pragma unroll
    for (int pass = 0; pass < 3; pass++) {
        const char* A = smem + ((pass == 2) ? N_A_LO : N_A_HI);
        const char* B = smem + ((pass == 1) ? N_B_LO : N_B_HI);
#pragma unroll
        for (int ks = 0; ks < 8; ks++) {
            int kb = ks * 32 + t4 * 4;
            uint32_t a[2][4];
#pragma unroll
            for (int mt = 0; mt < 2; mt++) {
                int row = wm * 32 + mt * 16 + g;
                a[mt][0] = *(const uint32_t*)(A + row * SROW + kb);
                a[mt][1] = *(const uint32_t*)(A + (row + 8) * SROW + kb);
                a[mt][2] = *(const uint32_t*)(A + row * SROW + kb + 16);
                a[mt][3] = *(const uint32_t*)(A + (row + 8) * SROW + kb + 16);
            }
#pragma unroll
            for (int nt = 0; nt < 8; nt++) {
                int n = wn * 64 + nt * 8 + g;
                uint32_t b0 = *(const uint32_t*)(B + n * SROW + kb);
                uint32_t b1 = *(const uint32_t*)(B + n * SROW + kb + 16);
                mma16816(acc[0][nt], a[0], b0, b1);
                mma16816(acc[1][nt], a[1], b0, b1);
            }
        }
    }

#pragma unroll
    for (int mt = 0; mt < 2; mt++) {
#pragma unroll
        for (int rh = 0; rh < 2; rh++) {
            int row = wm * 32 + mt * 16 + rh * 8 + g;
            int n = n0 + row;
            if (n >= N_NODES) continue;
            float* dst = g_P + (size_t)n * 256 + part * 128;
#pragma unroll
            for (int nt = 0; nt < 8; nt++) {
                int c = wn * 64 + nt * 8 + t4 * 2;
                *(float2*)(dst + c) = make_float2(acc[mt][nt][rh * 2 + 0], acc[mt][nt][rh * 2 + 1]);
            }
        }
    }
}

// ============ K2: persistent edge kernel, 2 CTAs/SM, M=64 tiles ============
#define E_B1   0
#define E_RAW  512                     // 64 x RROW(528) = 33792
#define E_B_HI (E_RAW + 33792)         // 32768
#define E_B_LO (E_B_HI + 32768)        // 32768
#define EDGE_SMEM (E_B_LO + 32768)     // 99840 B -> 2 CTAs/SM

__global__ __launch_bounds__(256, 2) void edge_kernel(const float* __restrict__ edge_feat,
                                                      const int* __restrict__ senders,
                                                      const int* __restrict__ receivers,
                                                      const float* __restrict__ b1) {
    extern __shared__ __align__(16) char smem[];
    uint32_t sb;
    asm("{ .reg .u64 t; cvta.to.shared.u64 t, %1; cvt.u32.u64 %0, t; }" : "=r"(sb) : "l"(smem));
    const int tid = threadIdx.x, wid = tid >> 5, lane = tid & 31;
    const int g = lane >> 2, t4 = lane & 3, wm = wid >> 2, wn = wid & 3;

    // one-time: packed weights + b1 into smem
    {
        const uint4* src = (const uint4*)&g_Bpack[0][0][0][0];  // 65536 B contiguous
        uint4* dst = (uint4*)(smem + E_B_HI);
#pragma unroll
        for (int i = tid; i < 4096; i += 256) dst[i] = src[i];
        if (tid < 128) ((float*)(smem + E_B1))[tid] = b1[tid];
    }

    // prefetch tile t raw fp32 rows into RAW (64 rows x 512 B, pitch RROW)
    auto prefetch = [&](int t) {
        if (t < N_TILES) {
            const char* src = (const char*)(edge_feat + (size_t)t * TILE_M * H);
#pragma unroll
            for (int j = 0; j < 8; j++) {
                int i = tid + j * 256;         // 2048 chunks of 16B
                int row = i >> 5, c16 = i & 31;
                cp16(sb + E_RAW + row * RROW + c16 * 16, src + (size_t)i * 16);
            }
        }
        CP_COMMIT();
    };

    prefetch(blockIdx.x);

    for (int t = blockIdx.x; t < N_TILES; t += EDGE_GRID) {
        CP_WAIT0();
        __syncthreads();   // RAW ready; everyone past previous epilogue

        // ---- GEMM: A split in regs from RAW; B from packed smem ----
        float acc[2][4][4];
#pragma unroll
        for (int mt = 0; mt < 2; mt++)
#pragma unroll
            for (int nt = 0; nt < 4; nt++)
#pragma unroll
                for (int q = 0; q < 4; q++) acc[mt][nt][q] = 0.f;

        const char* RAW = smem + E_RAW;
        const uint2* BH = (const uint2*)(smem + E_B_HI);
        const uint2* BL = (const uint2*)(smem + E_B_LO);
#pragma unroll
        for (int ks = 0; ks < 8; ks++) {
            const int kb = (ks * 16 + t4 * 2) * 4;
            uint32_t ah[2][4], al[2][4];
#pragma unroll
            for (int mt = 0; mt < 2; mt++) {
                int row = wm * 32 + mt * 16 + g;
                float2 f0 = *(const float2*)(RAW + row * RROW + kb);            // (row, k)
                float2 f1 = *(const float2*)(RAW + (row + 8) * RROW + kb);      // (row+8, k)
                float2 f2 = *(const float2*)(RAW + row * RROW + kb + 32);       // (row, k+8)
                float2 f3 = *(const float2*)(RAW + (row + 8) * RROW + kb + 32); // (row+8, k+8)
                unsigned short h0, l0, h1, l1;
                split2(f0.x, h0, l0); split2(f0.y, h1, l1);
                ah[mt][0] = (uint32_t)h0 | ((uint32_t)h1 << 16);
                al[mt][0] = (uint32_t)l0 | ((uint32_t)l1 << 16);
                split2(f1.x, h0, l0); split2(f1.y, h1, l1);
                ah[mt][1] = (uint32_t)h0 | ((uint32_t)h1 << 16);
                al[mt][1] = (uint32_t)l0 | ((uint32_t)l1 << 16);
                split2(f2.x, h0, l0); split2(f2.y, h1, l1);
                ah[mt][2] = (uint32_t)h0 | ((uint32_t)h1 << 16);
                al[mt][2] = (uint32_t)l0 | ((uint32_t)l1 << 16);
                split2(f3.x, h0, l0); split2(f3.y, h1, l1);
                ah[mt][3] = (uint32_t)h0 | ((uint32_t)h1 << 16);
                al[mt][3] = (uint32_t)l0 | ((uint32_t)l1 << 16);
            }
#pragma unroll
            for (int nt = 0; nt < 4; nt++) {
                int n = wn * 32 + nt * 8 + g;
                uint2 bh = BH[(ks * 128 + n) * 4 + t4];
                uint2 bl = BL[(ks * 128 + n) * 4 + t4];
#pragma unroll
                for (int mt = 0; mt < 2; mt++) {
                    mma16816(acc[mt][nt], ah[mt], bh.x, bh.y);
                    mma16816(acc[mt][nt], ah[mt], bl.x, bl.y);
                    mma16816(acc[mt][nt], al[mt], bh.x, bh.y);
                }
            }
        }
        __syncthreads();   // RAW fully consumed

        prefetch(t + EDGE_GRID);   // next tile's DRAM latency hides under epilogue

        // ---- epilogue: relu(D + P_s + P_r + b1) -> red.add accum[r] ----
        const size_t e0 = (size_t)t * TILE_M;
        const float* b1s = (const float*)(smem + E_B1);
#pragma unroll
        for (int mt = 0; mt < 2; mt++) {
#pragma unroll
            for (int rh = 0; rh < 2; rh++) {
                int row = wm * 32 + mt * 16 + rh * 8 + g;
                int s = __ldg(senders + e0 + row);
                int r = __ldg(receivers + e0 + row);
                const float* Ps = g_P + (size_t)s * 256;
                const float* Pr = g_P + (size_t)r * 256 + 128;
                float* ac = g_accum + (size_t)r * H;
#pragma unroll
                for (int nt = 0; nt < 4; nt++) {
                    int c = wn * 32 + nt * 8 + t4 * 2;
                    float2 ps = *(const float2*)(Ps + c);
                    float2 pr = *(const float2*)(Pr + c);
                    float2 bb = *(const float2*)(b1s + c);
                    float v0 = fmaxf(acc[mt][nt][rh * 2 + 0] + ps.x + pr.x + bb.x, 0.f);
                    float v1 = fmaxf(acc[mt][nt][rh * 2 + 1] + ps.y + pr.y + bb.y, 0.f);
                    asm volatile("red.global.add.v2.f32 [%0], {%1,%2};"
                                 :: "l"(ac + c), "f"(v0), "f"(v1) : "memory");
                }
            }
        }
    }
}

// ---------------- K3: layernorm ----------------
__global__ __launch_bounds__(256) void ln_kernel(const float* __restrict__ gamma,
                                                 const float* __restrict__ beta,
                                                 float* __restrict__ out) {
    const int wid = threadIdx.x >> 5, lid = threadIdx.x & 31;
    const int n = blockIdx.x * 8 + wid;
    if (n >= N_NODES) return;
    float4 v = ((const float4*)(g_accum + (size_t)n * H))[lid];
    float s = v.x + v.y + v.z + v.w;
#pragma unroll
    for (int o = 16; o > 0; o >>= 1) s += __shfl_xor_sync(0xFFFFFFFFu, s, o);
    float mu = s * (1.0f / H);
    float dx = v.x - mu, dy = v.y - mu, dz = v.z - mu, dw = v.w - mu;
    float ss = dx * dx + dy * dy + dz * dz + dw * dw;
#pragma unroll
    for (int o = 16; o > 0; o >>= 1) ss += __shfl_xor_sync(0xFFFFFFFFu, ss, o);
    float rs = rsqrtf(ss * (1.0f / H) + LN_EPS);
    float4 gm = ((const float4*)gamma)[lid];
    float4 b = ((const float4*)beta)[lid];
    float4 o4 = make_float4(gm.x * dx * rs + b.x, gm.y * dy * rs + b.y,
                            gm.z * dz * rs + b.z, gm.w * dw * rs + b.w);
    ((float4*)(out + (size_t)n * H))[lid] = o4;
}

// ---------------- launch ----------------
extern "C" void kernel_launch(void* const* d_in, const int* in_sizes, int n_in,
                              void* d_out, int out_size) {
    const float* x         = (const float*)d_in[0];
    const int*   senders   = (const int*)d_in[1];
    const int*   receivers = (const int*)d_in[2];
    const float* edge_feat = (const float*)d_in[3];
    const float* W1        = (const float*)d_in[4];
    const float* b1        = (const float*)d_in[5];
    const float* gamma     = (const float*)d_in[6];
    const float* beta      = (const float*)d_in[7];
    float* out = (float*)d_out;

    cudaFuncSetAttribute(node_proj_kernel, cudaFuncAttributeMaxDynamicSharedMemorySize, NODE_SMEM);
    cudaFuncSetAttribute(edge_kernel, cudaFuncAttributeMaxDynamicSharedMemorySize, EDGE_SMEM);

    splitw_kernel<<<192, 256>>>(W1);
    packw_kernel<<<16, 256>>>(W1);
    init_accum_kernel<<<(N_NODES * H / 4) / 256, 256>>>(x);
    node_proj_kernel<<<dim3((N_NODES + 127) / 128, 2), 256, NODE_SMEM>>>(x);
    edge_kernel<<<EDGE_GRID, 256, EDGE_SMEM>>>(edge_feat, senders, receivers, b1);
    ln_kernel<<<(N_NODES + 7) / 8, 256>>>(gamma, beta, out);
}

// round 6
// speedup vs baseline: 1.5334x; 1.0614x over previous
#include <cuda_runtime.h>
#include <cuda_fp16.h>
#include <cstdint>

#define N_NODES 50000
#define N_EDGES 800000
#define H 128
#define LN_EPS 1e-5f
#define TILE_M 64
#define N_TILES (N_EDGES / TILE_M)
#define EDGE_GRID 304

// ---------------- scratch (no cudaMalloc allowed) ----------------
__device__ __align__(256) float g_P[(size_t)N_NODES * 256];   // [n][0:128]=x@W1a, [n][128:256]=x@W1b
__device__ __align__(256) float g_accum[(size_t)N_NODES * H]; // residual + segment sum
__device__ __align__(256) __half g_Whi[2 * 128 * 128];        // node kernel: [part][n][k]
__device__ __align__(256) __half g_Wlo[2 * 128 * 128];
__device__ __align__(256) uint2 g_Bpack[2][8][128][4];        // edge W1c: [hi/lo][ks][n][t4]

#define SROW 272  // fp16 tile pitch (bytes)
#define RROW 528  // raw fp32 tile pitch (<=2-way conflicts on LDS.64)

__device__ __forceinline__ void split2h(float f, unsigned short& h, unsigned short& l) {
    __half hh = __float2half_rn(f);
    float r = f - __half2float(hh);
    h = __half_as_ushort(hh);
    l = __half_as_ushort(__float2half_rn(r));
}

__device__ __forceinline__ uint32_t packh2(float a, float b) {
    __half2 p = __floats2half2_rn(a, b);  // a -> lo, b -> hi
    return *(uint32_t*)&p;
}

__device__ __forceinline__ void mma16816(float* c, const uint32_t* a, uint32_t b0, uint32_t b1) {
    asm volatile("mma.sync.aligned.m16n8k16.row.col.f32.f16.f16.f32 "
                 "{%0,%1,%2,%3}, {%4,%5,%6,%7}, {%8,%9}, {%0,%1,%2,%3};"
                 : "+f"(c[0]), "+f"(c[1]), "+f"(c[2]), "+f"(c[3])
                 : "r"(a[0]), "r"(a[1]), "r"(a[2]), "r"(a[3]), "r"(b0), "r"(b1));
}

__device__ __forceinline__ void cp16(uint32_t dst, const void* src) {
    asm volatile("cp.async.cg.shared.global [%0], [%1], 16;" :: "r"(dst), "l"(src) : "memory");
}
#define CP_COMMIT() asm volatile("cp.async.commit_group;" ::: "memory")
#define CP_WAIT0()  asm volatile("cp.async.wait_group 0;" ::: "memory")

// ---------------- K_w: split node weights (parts 0,1) to fp16 hi/lo [part][n][k] ----------------
__global__ __launch_bounds__(256) void splitw_kernel(const float* __restrict__ W1) {
    int i = blockIdx.x * 256 + threadIdx.x;
    if (i >= 2 * 128 * 128) return;
    int part = i >> 14, nk = i & 16383, n = nk >> 7, k = nk & 127;
    float w = W1[(size_t)(part * 128 + k) * H + n];
    unsigned short h, l;
    split2h(w, h, l);
    g_Whi[i] = __ushort_as_half(h);
    g_Wlo[i] = __ushort_as_half(l);
}

// ---------------- K_w2: pack W1c (part 2) fragment-major fp16 hi/lo ----------------
__global__ __launch_bounds__(256) void packw_kernel(const float* __restrict__ W1) {
    int i = blockIdx.x * 256 + threadIdx.x;  // 4096 = 8 ks * 128 n * 4 t4
    if (i >= 4096) return;
    int ks = i >> 9, n = (i >> 2) & 127, t4 = i & 3;
    int k0 = ks * 16 + t4 * 2;
    unsigned short h[4], l[4];
    split2h(W1[(size_t)(256 + k0 + 0) * H + n], h[0], l[0]);
    split2h(W1[(size_t)(256 + k0 + 1) * H + n], h[1], l[1]);
    split2h(W1[(size_t)(256 + k0 + 8) * H + n], h[2], l[2]);
    split2h(W1[(size_t)(256 + k0 + 9) * H + n], h[3], l[3]);
    g_Bpack[0][ks][n][t4] =
        make_uint2((uint32_t)h[0] | ((uint32_t)h[1] << 16), (uint32_t)h[2] | ((uint32_t)h[3] << 16));
    g_Bpack[1][ks][n][t4] =
        make_uint2((uint32_t)l[0] | ((uint32_t)l[1] << 16), (uint32_t)l[2] | ((uint32_t)l[3] << 16));
}

// ---------------- K0: accum = x ----------------
__global__ __launch_bounds__(256) void init_accum_kernel(const float* __restrict__ x) {
    size_t i = (size_t)blockIdx.x * blockDim.x + threadIdx.x;
    ((float4*)g_accum)[i] = ((const float4*)x)[i];
}

// ---------------- K1: node projections P = x @ [W1a | W1b], 2-pass fp16 ----------------
#define N_A   0
#define N_B_HI (N_A + 34816)
#define N_B_LO (N_B_HI + 34816)
#define NODE_SMEM (N_B_LO + 34816)   // 104448 -> 2 CTAs/SM

__global__ __launch_bounds__(256, 2) void node_proj_kernel(const float* __restrict__ x) {
    extern __shared__ __align__(16) char smem[];
    const int tid = threadIdx.x, wid = tid >> 5, lane = tid & 31;
    const int g = lane >> 2, t4 = lane & 3, wm = wid & 3, wn = wid >> 2;
    const int part = blockIdx.y;
    const int n0 = blockIdx.x * 128;

    const uint2* wh = (const uint2*)(g_Whi + part * 16384);
    const uint2* wl = (const uint2*)(g_Wlo + part * 16384);
#pragma unroll
    for (int i = tid; i < 4096; i += 256) {
        uint32_t byte = (uint32_t)(i >> 5) * SROW + (uint32_t)(i & 31) * 8;
        *(uint2*)(smem + N_B_HI + byte) = wh[i];
        *(uint2*)(smem + N_B_LO + byte) = wl[i];
    }
    const float4* x4 = (const float4*)x;
#pragma unroll
    for (int i = tid; i < 4096; i += 256) {
        int row = i >> 5, cg = i & 31;
        int n = n0 + row;
        float4 v = (n < N_NODES) ? x4[(size_t)n * 32 + cg] : make_float4(0.f, 0.f, 0.f, 0.f);
        uint32_t byte = (uint32_t)row * SROW + (uint32_t)cg * 8;
        *(uint2*)(smem + N_A + byte) = make_uint2(packh2(v.x, v.y), packh2(v.z, v.w));
    }
    __syncthreads();

    float acc[2][8][4];
#pragma unroll
    for (int mt = 0; mt < 2; mt++)
#pragma unroll
        for (int nt = 0; nt < 8; nt++)
#pragma unroll
            for (int q = 0; q < 4; q++) acc[mt][nt][q] = 0.f;

    const char* A = smem + N_A;
#pragma unroll
    for (int ks = 0; ks < 8; ks++) {
        int kb = ks * 32 + t4 * 4;
        uint32_t a[2][4];
#pragma unroll
        for (int mt = 0; mt < 2; mt++) {
            int row = wm * 32 + mt * 16 + g;
            a[mt][0] = *(const uint32_t*)(A + row * SROW + kb);
            a[mt][1] = *(const uint32_t*)(A + (row + 8) * SROW + kb);
            a[mt][2] = *(const uint32_t*)(A + row * SROW + kb + 16);
            a[mt][3] = *(const uint32_t*)(A + (row + 8) * SROW + kb + 16);
        }
        const char* BH = smem + N_B_HI;
        const char* BL = smem + N_B_LO;
#pragma unroll
        for (int nt = 0; nt < 8; nt++) {
            int n = wn * 64 + nt * 8 + g;
            uint32_t bh0 = *(const uint32_t*)(BH + n * SROW + kb);
            uint32_t bh1 = *(const uint32_t*)(BH + n * SROW + kb + 16);
            uint32_t bl0 = *(const uint32_t*)(BL + n * SROW + kb);
            uint32_t bl1 = *(const uint32_t*)(BL + n * SROW + kb + 16);
            mma16816(acc[0][nt], a[0], bh0, bh1);
            mma16816(acc[0][nt], a[0], bl0, bl1);
            mma16816(acc[1][nt], a[1], bh0, bh1);
            mma16816(acc[1][nt], a[1], bl0, bl1);
        }
    }

#pragma unroll
    for (int mt = 0; mt < 2; mt++) {
#pragma unroll
        for (int rh = 0; rh < 2; rh++) {
            int row = wm * 32 + mt * 16 + rh * 8 + g;
            int n = n0 + row;
            if (n >= N_NODES) continue;
            float* dst = g_P + (size_t)n * 256 + part * 128;
#pragma unroll
            for (int nt = 0; nt < 8; nt++) {
                int c = wn * 64 + nt * 8 + t4 * 2;
                *(float2*)(dst + c) = make_float2(acc[mt][nt][rh * 2 + 0], acc[mt][nt][rh * 2 + 1]);
            }
        }
    }
}

// ============ K2: persistent edge kernel, 2 CTAs/SM, M=64, 2-pass fp16 ============
#define E_B1   0
#define E_RAW  512                     // 64 x RROW(528) = 33792
#define E_B_HI (E_RAW + 33792)         // 32768
#define E_B_LO (E_B_HI + 32768)        // 32768
#define EDGE_SMEM (E_B_LO + 32768)     // 99840 B -> 2 CTAs/SM

__global__ __launch_bounds__(256, 2) void edge_kernel(const float* __restrict__ edge_feat,
                                                      const int* __restrict__ senders,
                                                      const int* __restrict__ receivers,
                                                      const float* __restrict__ b1) {
    extern __shared__ __align__(16) char smem[];
    uint32_t sb;
    asm("{ .reg .u64 t; cvta.to.shared.u64 t, %1; cvt.u32.u64 %0, t; }" : "=r"(sb) : "l"(smem));
    const int tid = threadIdx.x, wid = tid >> 5, lane = tid & 31;
    const int g = lane >> 2, t4 = lane & 3, wm = wid >> 2, wn = wid & 3;

    // one-time: packed weights + b1 into smem
    {
        const uint4* src = (const uint4*)&g_Bpack[0][0][0][0];  // 65536 B contiguous
        uint4* dst = (uint4*)(smem + E_B_HI);
#pragma unroll
        for (int i = tid; i < 4096; i += 256) dst[i] = src[i];
        if (tid < 128) ((float*)(smem + E_B1))[tid] = b1[tid];
    }

    auto prefetch = [&](int t) {
        if (t < N_TILES) {
            const char* src = (const char*)(edge_feat + (size_t)t * TILE_M * H);
#pragma unroll
            for (int j = 0; j < 8; j++) {
                int i = tid + j * 256;
                int row = i >> 5, c16 = i & 31;
                cp16(sb + E_RAW + row * RROW + c16 * 16, src + (size_t)i * 16);
            }
        }
        CP_COMMIT();
    };

    prefetch(blockIdx.x);

    for (int t = blockIdx.x; t < N_TILES; t += EDGE_GRID) {
        CP_WAIT0();
        __syncthreads();   // RAW ready; everyone past previous epilogue

        float acc[2][4][4];
#pragma unroll
        for (int mt = 0; mt < 2; mt++)
#pragma unroll
            for (int nt = 0; nt < 4; nt++)
#pragma unroll
                for (int q = 0; q < 4; q++) acc[mt][nt][q] = 0.f;

        const char* RAW = smem + E_RAW;
        const uint2* BH = (const uint2*)(smem + E_B_HI);
        const uint2* BL = (const uint2*)(smem + E_B_LO);
#pragma unroll
        for (int ks = 0; ks < 8; ks++) {
            const int kb = (ks * 16 + t4 * 2) * 4;
            uint32_t a[2][4];
#pragma unroll
            for (int mt = 0; mt < 2; mt++) {
                int row = wm * 32 + mt * 16 + g;
                float2 f0 = *(const float2*)(RAW + row * RROW + kb);
                float2 f1 = *(const float2*)(RAW + (row + 8) * RROW + kb);
                float2 f2 = *(const float2*)(RAW + row * RROW + kb + 32);
                float2 f3 = *(const float2*)(RAW + (row + 8) * RROW + kb + 32);
                a[mt][0] = packh2(f0.x, f0.y);
                a[mt][1] = packh2(f1.x, f1.y);
                a[mt][2] = packh2(f2.x, f2.y);
                a[mt][3] = packh2(f3.x, f3.y);
            }
#pragma unroll
            for (int nt = 0; nt < 4; nt++) {
                int n = wn * 32 + nt * 8 + g;
                uint2 bh = BH[(ks * 128 + n) * 4 + t4];
                uint2 bl = BL[(ks * 128 + n) * 4 + t4];
#pragma unroll
                for (int mt = 0; mt < 2; mt++) {
                    mma16816(acc[mt][nt], a[mt], bh.x, bh.y);
                    mma16816(acc[mt][nt], a[mt], bl.x, bl.y);
                }
            }
        }
        __syncthreads();   // RAW fully consumed

        prefetch(t + EDGE_GRID);   // next tile's DRAM latency hides under epilogue

        // ---- epilogue: relu(D + P_s + P_r + b1) -> red.add accum[r] ----
        const size_t e0 = (size_t)t * TILE_M;
        const float* b1s = (const float*)(smem + E_B1);
#pragma unroll
        for (int mt = 0; mt < 2; mt++) {
#pragma unroll
            for (int rh = 0; rh < 2; rh++) {
                int row = wm * 32 + mt * 16 + rh * 8 + g;
                int s = __ldg(senders + e0 + row);
                int r = __ldg(receivers + e0 + row);
                const float* Ps = g_P + (size_t)s * 256;
                const float* Pr = g_P + (size_t)r * 256 + 128;
                float* ac = g_accum + (size_t)r * H;
#pragma unroll
                for (int nt = 0; nt < 4; nt++) {
                    int c = wn * 32 + nt * 8 + t4 * 2;
                    float2 ps = *(const float2*)(Ps + c);
                    float2 pr = *(const float2*)(Pr + c);
                    float2 bb = *(const float2*)(b1s + c);
                    float v0 = fmaxf(acc[mt][nt][rh * 2 + 0] + ps.x + pr.x + bb.x, 0.f);
                    float v1 = fmaxf(acc[mt][nt][rh * 2 + 1] + ps.y + pr.y + bb.y, 0.f);
                    asm volatile("red.global.add.v2.f32 [%0], {%1,%2};"
                                 :: "l"(ac + c), "f"(v0), "f"(v1) : "memory");
                }
            }
        }
    }
}

// ---------------- K3: layernorm ----------------
__global__ __launch_bounds__(256) void ln_kernel(const float* __restrict__ gamma,
                                                 const float* __restrict__ beta,
                                                 float* __restrict__ out) {
    const int wid = threadIdx.x >> 5, lid = threadIdx.x & 31;
    const int n = blockIdx.x * 8 + wid;
    if (n >= N_NODES) return;
    float4 v = ((const float4*)(g_accum + (size_t)n * H))[lid];
    float s = v.x + v.y + v.z + v.w;
#pragma unroll
    for (int o = 16; o > 0; o >>= 1) s += __shfl_xor_sync(0xFFFFFFFFu, s, o);
    float mu = s * (1.0f / H);
    float dx = v.x - mu, dy = v.y - mu, dz = v.z - mu, dw = v.w - mu;
    float ss = dx * dx + dy * dy + dz * dz + dw * dw;
#pragma unroll
    for (int o = 16; o > 0; o >>= 1) ss += __shfl_xor_sync(0xFFFFFFFFu, ss, o);
    float rs = rsqrtf(ss * (1.0f / H) + LN_EPS);
    float4 gm = ((const float4*)gamma)[lid];
    float4 b = ((const float4*)beta)[lid];
    float4 o4 = make_float4(gm.x * dx * rs + b.x, gm.y * dy * rs + b.y,
                            gm.z * dz * rs + b.z, gm.w * dw * rs + b.w);
    ((float4*)(out + (size_t)n * H))[lid] = o4;
}

// ---------------- launch ----------------
extern "C" void kernel_launch(void* const* d_in, const int* in_sizes, int n_in,
                              void* d_out, int out_size) {
    const float* x         = (const float*)d_in[0];
    const int*   senders   = (const int*)d_in[1];
    const int*   receivers = (const int*)d_in[2];
    const float* edge_feat = (const float*)d_in[3];
    const float* W1        = (const float*)d_in[4];
    const float* b1        = (const float*)d_in[5];
    const float* gamma     = (const float*)d_in[6];
    const float* beta      = (const float*)d_in[7];
    float* out = (float*)d_out;

    cudaFuncSetAttribute(node_proj_kernel, cudaFuncAttributeMaxDynamicSharedMemorySize, NODE_SMEM);
    cudaFuncSetAttribute(edge_kernel, cudaFuncAttributeMaxDynamicSharedMemorySize, EDGE_SMEM);

    splitw_kernel<<<128, 256>>>(W1);
    packw_kernel<<<16, 256>>>(W1);
    init_accum_kernel<<<(N_NODES * H / 4) / 256, 256>>>(x);
    node_proj_kernel<<<dim3((N_NODES + 127) / 128, 2), 256, NODE_SMEM>>>(x);
    edge_kernel<<<EDGE_GRID, 256, EDGE_SMEM>>>(edge_feat, senders, receivers, b1);
    ln_kernel<<<(N_NODES + 7) / 8, 256>>>(gamma, beta, out);
}

// round 8
// speedup vs baseline: 3.0431x; 1.9845x over previous
#include <cuda_runtime.h>
#include <cuda_fp16.h>
#include <cstdint>

#define N_NODES 50000
#define N_EDGES 800000
#define H 128
#define LN_EPS 1e-5f
#define TILE_M 64
#define N_TILES (N_EDGES / TILE_M)
#define EDGE_GRID 304

// ---------------- scratch (no cudaMalloc allowed) ----------------
__device__ __align__(256) float g_P[(size_t)N_NODES * 256];   // [n][0:128]=x@W1a, [n][128:256]=x@W1b
__device__ __align__(256) float g_accum[(size_t)N_NODES * H]; // residual + segment sum
__device__ __align__(256) __half g_Whi[2 * 128 * 128];        // node kernel: [part][n][k] fp16
__device__ __align__(256) uint2 g_Bpack[8][128][4];           // edge W1c frag-major fp16: [ks][n][t4]

#define SROW 272  // node fp16 tile pitch (bytes)
#define AROW 272  // edge A16 pitch (16B-mult, ldmatrix conflict-free)
#define MROW 272  // edge MSG fp16 pitch

__device__ __forceinline__ uint32_t packh2(float a, float b) {
    __half2 p = __floats2half2_rn(a, b);  // a -> lo, b -> hi
    return *(uint32_t*)&p;
}

__device__ __forceinline__ void mma16816(float* c, const uint32_t* a, uint32_t b0, uint32_t b1) {
    asm volatile("mma.sync.aligned.m16n8k16.row.col.f32.f16.f16.f32 "
                 "{%0,%1,%2,%3}, {%4,%5,%6,%7}, {%8,%9}, {%0,%1,%2,%3};"
                 : "+f"(c[0]), "+f"(c[1]), "+f"(c[2]), "+f"(c[3])
                 : "r"(a[0]), "r"(a[1]), "r"(a[2]), "r"(a[3]), "r"(b0), "r"(b1));
}

#define LDSM4(r, addr)                                                                      \
    asm volatile("ldmatrix.sync.aligned.m8n8.x4.shared.b16 {%0,%1,%2,%3}, [%4];"            \
                 : "=r"((r)[0]), "=r"((r)[1]), "=r"((r)[2]), "=r"((r)[3]) : "r"(addr))

__device__ __forceinline__ void cp16(uint32_t dst, const void* src) {
    asm volatile("cp.async.cg.shared.global [%0], [%1], 16;" :: "r"(dst), "l"(src) : "memory");
}
#define CP_COMMIT() asm volatile("cp.async.commit_group;" ::: "memory")
#define CP_WAIT0()  asm volatile("cp.async.wait_group 0;" ::: "memory")

// ---------------- K_w: node weights (parts 0,1) -> fp16 [part][n][k] ----------------
__global__ __launch_bounds__(256) void splitw_kernel(const float* __restrict__ W1) {
    int i = blockIdx.x * 256 + threadIdx.x;
    if (i >= 2 * 128 * 128) return;
    int part = i >> 14, nk = i & 16383, n = nk >> 7, k = nk & 127;
    g_Whi[i] = __float2half_rn(W1[(size_t)(part * 128 + k) * H + n]);
}

// ---------------- K_w2: pack W1c (part 2) fragment-major fp16 ----------------
__global__ __launch_bounds__(256) void packw_kernel(const float* __restrict__ W1) {
    int i = blockIdx.x * 256 + threadIdx.x;  // 4096 = 8 ks * 128 n * 4 t4
    if (i >= 4096) return;
    int ks = i >> 9, n = (i >> 2) & 127, t4 = i & 3;
    int k0 = ks * 16 + t4 * 2;
    uint32_t w0 = packh2(W1[(size_t)(256 + k0 + 0) * H + n], W1[(size_t)(256 + k0 + 1) * H + n]);
    uint32_t w1 = packh2(W1[(size_t)(256 + k0 + 8) * H + n], W1[(size_t)(256 + k0 + 9) * H + n]);
    g_Bpack[ks][n][t4] = make_uint2(w0, w1);
}

// ---------------- K0: accum = x ----------------
__global__ __launch_bounds__(256) void init_accum_kernel(const float* __restrict__ x) {
    size_t i = (size_t)blockIdx.x * blockDim.x + threadIdx.x;
    ((float4*)g_accum)[i] = ((const float4*)x)[i];
}

// ---------------- K1: node projections P = x @ [W1a | W1b], fp16 single ----------------
#define N_A   0
#define N_B   (N_A + 34816)
#define NODE_SMEM (N_B + 34816)   // 69632 -> 2 CTAs/SM

__global__ __launch_bounds__(256, 2) void node_proj_kernel(const float* __restrict__ x) {
    extern __shared__ __align__(16) char smem[];
    const int tid = threadIdx.x, wid = tid >> 5, lane = tid & 31;
    const int g = lane >> 2, t4 = lane & 3, wm = wid & 3, wn = wid >> 2;
    const int part = blockIdx.y;
    const int n0 = blockIdx.x * 128;

    const uint2* wh = (const uint2*)(g_Whi + part * 16384);
#pragma unroll
    for (int i = tid; i < 4096; i += 256) {
        uint32_t byte = (uint32_t)(i >> 5) * SROW + (uint32_t)(i & 31) * 8;
        *(uint2*)(smem + N_B + byte) = wh[i];
    }
    const float4* x4 = (const float4*)x;
#pragma unroll
    for (int i = tid; i < 4096; i += 256) {
        int row = i >> 5, cg = i & 31;
        int n = n0 + row;
        float4 v = (n < N_NODES) ? x4[(size_t)n * 32 + cg] : make_float4(0.f, 0.f, 0.f, 0.f);
        uint32_t byte = (uint32_t)row * SROW + (uint32_t)cg * 8;
        *(uint2*)(smem + N_A + byte) = make_uint2(packh2(v.x, v.y), packh2(v.z, v.w));
    }
    __syncthreads();

    float acc[2][8][4];
#pragma unroll
    for (int mt = 0; mt < 2; mt++)
#pragma unroll
        for (int nt = 0; nt < 8; nt++)
#pragma unroll
            for (int q = 0; q < 4; q++) acc[mt][nt][q] = 0.f;

    const char* A = smem + N_A;
    const char* B = smem + N_B;
#pragma unroll
    for (int ks = 0; ks < 8; ks++) {
        int kb = ks * 32 + t4 * 4;
        uint32_t a[2][4];
#pragma unroll
        for (int mt = 0; mt < 2; mt++) {
            int row = wm * 32 + mt * 16 + g;
            a[mt][0] = *(const uint32_t*)(A + row * SROW + kb);
            a[mt][1] = *(const uint32_t*)(A + (row + 8) * SROW + kb);
            a[mt][2] = *(const uint32_t*)(A + row * SROW + kb + 16);
            a[mt][3] = *(const uint32_t*)(A + (row + 8) * SROW + kb + 16);
        }
#pragma unroll
        for (int nt = 0; nt < 8; nt++) {
            int n = wn * 64 + nt * 8 + g;
            uint32_t b0 = *(const uint32_t*)(B + n * SROW + kb);
            uint32_t b1 = *(const uint32_t*)(B + n * SROW + kb + 16);
            mma16816(acc[0][nt], a[0], b0, b1);
            mma16816(acc[1][nt], a[1], b0, b1);
        }
    }

#pragma unroll
    for (int mt = 0; mt < 2; mt++) {
#pragma unroll
        for (int rh = 0; rh < 2; rh++) {
            int row = wm * 32 + mt * 16 + rh * 8 + g;
            int n = n0 + row;
            if (n >= N_NODES) continue;
            float* dst = g_P + (size_t)n * 256 + part * 128;
#pragma unroll
            for (int nt = 0; nt < 8; nt++) {
                int c = wn * 64 + nt * 8 + t4 * 2;
                *(float2*)(dst + c) = make_float2(acc[mt][nt][rh * 2 + 0], acc[mt][nt][rh * 2 + 1]);
            }
        }
    }
}

// ============ K2: persistent edge kernel, 2 CTAs/SM, fp16 + ldmatrix + staged epilogue ============
#define E_RAW  0                       // 64 x 512 = 32768 (contiguous raw fp32 tile)
#define E_A16  32768                   // 64 x AROW(272) = 17408 (fp16 A)
#define E_B16  (E_A16 + 17408)         // 32768 (frag-major fp16 W1c)
#define E_MSG  (E_B16 + 32768)         // 64 x MROW(272) = 17408 (fp16 D staging)
#define EDGE_SMEM (E_MSG + 17408)      // 100352 -> 2 CTAs/SM

__global__ __launch_bounds__(256, 2) void edge_kernel(const float* __restrict__ edge_feat,
                                                      const int* __restrict__ senders,
                                                      const int* __restrict__ receivers,
                                                      const float* __restrict__ b1) {
    extern __shared__ __align__(16) char smem[];
    uint32_t sb;
    asm("{ .reg .u64 t; cvta.to.shared.u64 t, %1; cvt.u32.u64 %0, t; }" : "=r"(sb) : "l"(smem));
    const int tid = threadIdx.x, wid = tid >> 5, lane = tid & 31;
    const int g = lane >> 2, t4 = lane & 3, wm = wid >> 2, wn = wid & 3;

    // one-time: packed W1c into smem; b1 into registers (lane owns cols 4l..4l+3)
    {
        const uint4* src = (const uint4*)&g_Bpack[0][0][0];  // 32768 B
        uint4* dst = (uint4*)(smem + E_B16);
#pragma unroll
        for (int i = tid; i < 2048; i += 256) dst[i] = src[i];
    }
    const float4 b1v = __ldg((const float4*)b1 + lane);

    // ldmatrix lane addressing: matrix j from lanes 8j..8j+7
    // j=0: rows 0-7 k0-7 | j=1: rows 8-15 k0-7 | j=2: rows 0-7 k8-15 | j=3: rows 8-15 k8-15
    const int lrow = lane & 7, lsel = lane >> 3;
    const uint32_t a_lane_off =
        (uint32_t)(((lsel & 1) * 8 + lrow) * AROW + (lsel >> 1) * 16);
    const uint32_t a_addr0 = sb + E_A16 + (wm * 32 + 0) * AROW + a_lane_off;
    const uint32_t a_addr1 = sb + E_A16 + (wm * 32 + 16) * AROW + a_lane_off;

    // prefetch: raw tile is 64 rows x 512 B, fully contiguous -> linear copy
    auto prefetch = [&](int t) {
        if (t < N_TILES) {
            const char* src = (const char*)(edge_feat + (size_t)t * TILE_M * H);
#pragma unroll
            for (int j = 0; j < 8; j++) {
                int i = tid + j * 256;
                cp16(sb + E_RAW + i * 16, src + (size_t)i * 16);
            }
        }
        CP_COMMIT();
    };

    prefetch(blockIdx.x);

    for (int t = blockIdx.x; t < N_TILES; t += EDGE_GRID) {
        CP_WAIT0();
        __syncthreads();   // RAW ready; all threads past previous epilogue

        // ---- convert RAW fp32 -> A16 fp16: 64 rows x 32 float4/row = 2048 float4 ----
#pragma unroll
        for (int j = 0; j < 8; j++) {
            int i = tid + j * 256;
            int row = i >> 5, c4 = i & 31;
            float4 v = *(const float4*)(smem + E_RAW + (size_t)i * 16);
            *(uint2*)(smem + E_A16 + row * AROW + c4 * 8) =
                make_uint2(packh2(v.x, v.y), packh2(v.z, v.w));
        }
        __syncthreads();   // A16 ready; RAW fully consumed

        prefetch(t + EDGE_GRID);   // overwrites RAW; hidden under GEMM + epilogue

        // ---- GEMM: ldmatrix A, frag-major B, single fp16 pass ----
        float acc[2][4][4];
#pragma unroll
        for (int mt = 0; mt < 2; mt++)
#pragma unroll
            for (int nt = 0; nt < 4; nt++)
#pragma unroll
                for (int q = 0; q < 4; q++) acc[mt][nt][q] = 0.f;

        const uint2* B16 = (const uint2*)(smem + E_B16);
#pragma unroll
        for (int ks = 0; ks < 8; ks++) {
            uint32_t a0[4], a1[4];
            LDSM4(a0, a_addr0 + ks * 32);
            LDSM4(a1, a_addr1 + ks * 32);
#pragma unroll
            for (int nt = 0; nt < 4; nt++) {
                int n = wn * 32 + nt * 8 + g;
                uint2 b = B16[(ks * 128 + n) * 4 + t4];
                mma16816(acc[0][nt], a0, b.x, b.y);
                mma16816(acc[1][nt], a1, b.x, b.y);
            }
        }

        // ---- stage D to MSG (fp16, conflict-free STS.32) ----
#pragma unroll
        for (int mt = 0; mt < 2; mt++)
#pragma unroll
            for (int nt = 0; nt < 4; nt++)
#pragma unroll
                for (int rh = 0; rh < 2; rh++) {
                    int row = wm * 32 + mt * 16 + rh * 8 + g;
                    int c = wn * 32 + nt * 8 + t4 * 2;
                    *(uint32_t*)(smem + E_MSG + row * MROW + c * 2) =
                        packh2(acc[mt][nt][rh * 2 + 0], acc[mt][nt][rh * 2 + 1]);
                }
        __syncthreads();   // MSG complete

        // ---- epilogue: warp-per-edge, fully coalesced gathers + RED.128 ----
        const size_t e0 = (size_t)t * TILE_M;
#pragma unroll
        for (int j = 0; j < 8; j++) {
            int row = wid * 8 + j;
            size_t e = e0 + row;
            int s = __ldg(senders + e);
            int r = __ldg(receivers + e);
            uint2 mm = *(const uint2*)(smem + E_MSG + row * MROW + lane * 8);
            float2 f0 = __half22float2(*(__half2*)&mm.x);
            float2 f1 = __half22float2(*(__half2*)&mm.y);
            float4 ps = __ldg((const float4*)(g_P + (size_t)s * 256) + lane);
            float4 pr = __ldg((const float4*)(g_P + (size_t)r * 256 + 128) + lane);
            float v0 = fmaxf(f0.x + ps.x + pr.x + b1v.x, 0.f);
            float v1 = fmaxf(f0.y + ps.y + pr.y + b1v.y, 0.f);
            float v2 = fmaxf(f1.x + ps.z + pr.z + b1v.z, 0.f);
            float v3 = fmaxf(f1.y + ps.w + pr.w + b1v.w, 0.f);
            asm volatile("red.global.add.v4.f32 [%0], {%1,%2,%3,%4};"
                         :: "l"(g_accum + (size_t)r * H + lane * 4),
                            "f"(v0), "f"(v1), "f"(v2), "f"(v3) : "memory");
        }
    }
}

// ---------------- K3: layernorm ----------------
__global__ __launch_bounds__(256) void ln_kernel(const float* __restrict__ gamma,
                                                 const float* __restrict__ beta,
                                                 float* __restrict__ out) {
    const int wid = threadIdx.x >> 5, lid = threadIdx.x & 31;
    const int n = blockIdx.x * 8 + wid;
    if (n >= N_NODES) return;
    float4 v = ((const float4*)(g_accum + (size_t)n * H))[lid];
    float s = v.x + v.y + v.z + v.w;
#pragma unroll
    for (int o = 16; o > 0; o >>= 1) s += __shfl_xor_sync(0xFFFFFFFFu, s, o);
    float mu = s * (1.0f / H);
    float dx = v.x - mu, dy = v.y - mu, dz = v.z - mu, dw = v.w - mu;
    float ss = dx * dx + dy * dy + dz * dz + dw * dw;
#pragma unroll
    for (int o = 16; o > 0; o >>= 1) ss += __shfl_xor_sync(0xFFFFFFFFu, ss, o);
    float rs = rsqrtf(ss * (1.0f / H) + LN_EPS);
    float4 gm = ((const float4*)gamma)[lid];
    float4 b = ((const float4*)beta)[lid];
    float4 o4 = make_float4(gm.x * dx * rs + b.x, gm.y * dy * rs + b.y,
                            gm.z * dz * rs + b.z, gm.w * dw * rs + b.w);
    ((float4*)(out + (size_t)n * H))[lid] = o4;
}

// ---------------- launch ----------------
extern "C" void kernel_launch(void* const* d_in, const int* in_sizes, int n_in,
                              void* d_out, int out_size) {
    const float* x         = (const float*)d_in[0];
    const int*   senders   = (const int*)d_in[1];
    const int*   receivers = (const int*)d_in[2];
    const float* edge_feat = (const float*)d_in[3];
    const float* W1        = (const float*)d_in[4];
    const float* b1        = (const float*)d_in[5];
    const float* gamma     = (const float*)d_in[6];
    const float* beta      = (const float*)d_in[7];
    float* out = (float*)d_out;

    cudaFuncSetAttribute(node_proj_kernel, cudaFuncAttributeMaxDynamicSharedMemorySize, NODE_SMEM);
    cudaFuncSetAttribute(edge_kernel, cudaFuncAttributeMaxDynamicSharedMemorySize, EDGE_SMEM);

    splitw_kernel<<<128, 256>>>(W1);
    packw_kernel<<<16, 256>>>(W1);
    init_accum_kernel<<<(N_NODES * H / 4) / 256, 256>>>(x);
    node_proj_kernel<<<dim3((N_NODES + 127) / 128, 2), 256, NODE_SMEM>>>(x);
    edge_kernel<<<EDGE_GRID, 256, EDGE_SMEM>>>(edge_feat, senders, receivers, b1);
    ln_kernel<<<(N_NODES + 7) / 8, 256>>>(gamma, beta, out);
}

// round 10
// speedup vs baseline: 3.7114x; 1.2196x over previous
#include <cuda_runtime.h>
#include <cuda_fp16.h>
#include <cstdint>

#define N_NODES 50000
#define N_EDGES 800000
#define H 128
#define LN_EPS 1e-5f
#define TILE_M 64
#define N_TILES (N_EDGES / TILE_M)
#define EDGE_GRID 304

// ---------------- scratch (no cudaMalloc allowed) ----------------
__device__ __align__(256) __half g_Ph[(size_t)N_NODES * 256]; // fp16: [n][0:128]=x@W1a, [128:256]=x@W1b+b1
__device__ __align__(256) float g_accum[(size_t)N_NODES * H]; // residual + segment sum
__device__ __align__(256) __half g_Whi[2 * 128 * 128];        // node kernel: [part][n][k] fp16
__device__ __align__(256) uint2 g_Bpack[8][128][4];           // edge W1c frag-major fp16: [ks][n][t4]

#define SROW 272  // node fp16 tile pitch (bytes)
#define AROW 272  // edge A16 pitch (16B-mult, ldmatrix conflict-free)
#define MROW 272  // edge MSG fp16 pitch

__device__ __forceinline__ uint32_t packh2(float a, float b) {
    __half2 p = __floats2half2_rn(a, b);  // a -> lo, b -> hi
    return *(uint32_t*)&p;
}

__device__ __forceinline__ void mma16816(float* c, const uint32_t* a, uint32_t b0, uint32_t b1) {
    asm volatile("mma.sync.aligned.m16n8k16.row.col.f32.f16.f16.f32 "
                 "{%0,%1,%2,%3}, {%4,%5,%6,%7}, {%8,%9}, {%0,%1,%2,%3};"
                 : "+f"(c[0]), "+f"(c[1]), "+f"(c[2]), "+f"(c[3])
                 : "r"(a[0]), "r"(a[1]), "r"(a[2]), "r"(a[3]), "r"(b0), "r"(b1));
}

#define LDSM4(r, addr)                                                                      \
    asm volatile("ldmatrix.sync.aligned.m8n8.x4.shared.b16 {%0,%1,%2,%3}, [%4];"            \
                 : "=r"((r)[0]), "=r"((r)[1]), "=r"((r)[2]), "=r"((r)[3]) : "r"(addr))

__device__ __forceinline__ void cp16(uint32_t dst, const void* src) {
    asm volatile("cp.async.cg.shared.global [%0], [%1], 16;" :: "r"(dst), "l"(src) : "memory");
}
#define CP_COMMIT() asm volatile("cp.async.commit_group;" ::: "memory")
#define CP_WAIT0()  asm volatile("cp.async.wait_group 0;" ::: "memory")

// ---------------- K_w: node weights (parts 0,1) -> fp16 [part][n][k] ----------------
__global__ __launch_bounds__(256) void splitw_kernel(const float* __restrict__ W1) {
    int i = blockIdx.x * 256 + threadIdx.x;
    if (i >= 2 * 128 * 128) return;
    int part = i >> 14, nk = i & 16383, n = nk >> 7, k = nk & 127;
    g_Whi[i] = __float2half_rn(W1[(size_t)(part * 128 + k) * H + n]);
}

// ---------------- K_w2: pack W1c (part 2) fragment-major fp16 ----------------
__global__ __launch_bounds__(256) void packw_kernel(const float* __restrict__ W1) {
    int i = blockIdx.x * 256 + threadIdx.x;  // 4096 = 8 ks * 128 n * 4 t4
    if (i >= 4096) return;
    int ks = i >> 9, n = (i >> 2) & 127, t4 = i & 3;
    int k0 = ks * 16 + t4 * 2;
    uint32_t w0 = packh2(W1[(size_t)(256 + k0 + 0) * H + n], W1[(size_t)(256 + k0 + 1) * H + n]);
    uint32_t w1 = packh2(W1[(size_t)(256 + k0 + 8) * H + n], W1[(size_t)(256 + k0 + 9) * H + n]);
    g_Bpack[ks][n][t4] = make_uint2(w0, w1);
}

// ---------------- K1: node projections P = x @ [W1a | W1b(+b1)], fp16, writes accum=x ----------------
#define N_A   0
#define N_B   (N_A + 34816)
#define NODE_SMEM (N_B + 34816)   // 69632 -> 2 CTAs/SM

__global__ __launch_bounds__(256, 2) void node_proj_kernel(const float* __restrict__ x,
                                                           const float* __restrict__ b1) {
    extern __shared__ __align__(16) char smem[];
    const int tid = threadIdx.x, wid = tid >> 5, lane = tid & 31;
    const int g = lane >> 2, t4 = lane & 3, wm = wid & 3, wn = wid >> 2;
    const int part = blockIdx.y;
    const int n0 = blockIdx.x * 128;

    const uint2* wh = (const uint2*)(g_Whi + part * 16384);
#pragma unroll
    for (int i = tid; i < 4096; i += 256) {
        uint32_t byte = (uint32_t)(i >> 5) * SROW + (uint32_t)(i & 31) * 8;
        *(uint2*)(smem + N_B + byte) = wh[i];
    }
    const float4* x4 = (const float4*)x;
#pragma unroll
    for (int i = tid; i < 4096; i += 256) {
        int row = i >> 5, cg = i & 31;
        int n = n0 + row;
        float4 v = (n < N_NODES) ? x4[(size_t)n * 32 + cg] : make_float4(0.f, 0.f, 0.f, 0.f);
        uint32_t byte = (uint32_t)row * SROW + (uint32_t)cg * 8;
        *(uint2*)(smem + N_A + byte) = make_uint2(packh2(v.x, v.y), packh2(v.z, v.w));
        if (part == 0 && n < N_NODES)
            ((float4*)g_accum)[(size_t)n * 32 + cg] = v;  // residual init fused here
    }
    __syncthreads();

    float acc[2][8][4];
#pragma unroll
    for (int mt = 0; mt < 2; mt++)
#pragma unroll
        for (int nt = 0; nt < 8; nt++)
#pragma unroll
            for (int q = 0; q < 4; q++) acc[mt][nt][q] = 0.f;

    const char* A = smem + N_A;
    const char* B = smem + N_B;
#pragma unroll
    for (int ks = 0; ks < 8; ks++) {
        int kb = ks * 32 + t4 * 4;
        uint32_t a[2][4];
#pragma unroll
        for (int mt = 0; mt < 2; mt++) {
            int row = wm * 32 + mt * 16 + g;
            a[mt][0] = *(const uint32_t*)(A + row * SROW + kb);
            a[mt][1] = *(const uint32_t*)(A + (row + 8) * SROW + kb);
            a[mt][2] = *(const uint32_t*)(A + row * SROW + kb + 16);
            a[mt][3] = *(const uint32_t*)(A + (row + 8) * SROW + kb + 16);
        }
#pragma unroll
        for (int nt = 0; nt < 8; nt++) {
            int n = wn * 64 + nt * 8 + g;
            uint32_t b0 = *(const uint32_t*)(B + n * SROW + kb);
            uint32_t b1r = *(const uint32_t*)(B + n * SROW + kb + 16);
            mma16816(acc[0][nt], a[0], b0, b1r);
            mma16816(acc[1][nt], a[1], b0, b1r);
        }
    }

    // epilogue: fp16 store to g_Ph; part 1 folds b1 in (each msg adds exactly one Pr)
#pragma unroll
    for (int mt = 0; mt < 2; mt++) {
#pragma unroll
        for (int rh = 0; rh < 2; rh++) {
            int row = wm * 32 + mt * 16 + rh * 8 + g;
            int n = n0 + row;
            if (n >= N_NODES) continue;
            __half* dst = g_Ph + (size_t)n * 256 + part * 128;
#pragma unroll
            for (int nt = 0; nt < 8; nt++) {
                int c = wn * 64 + nt * 8 + t4 * 2;
                float v0 = acc[mt][nt][rh * 2 + 0];
                float v1 = acc[mt][nt][rh * 2 + 1];
                if (part == 1) {
                    float2 bb = *(const float2*)(b1 + c);
                    v0 += bb.x;
                    v1 += bb.y;
                }
                *(uint32_t*)(dst + c) = packh2(v0, v1);
            }
        }
    }
}

// ============ K2: persistent edge kernel, 2 CTAs/SM, fp16 + ldmatrix + staged epilogue ============
#define E_RAW  0                       // 64 x 512 = 32768 (contiguous raw fp32 tile)
#define E_A16  32768                   // 64 x AROW(272) = 17408 (fp16 A)
#define E_B16  (E_A16 + 17408)         // 32768 (frag-major fp16 W1c)
#define E_MSG  (E_B16 + 32768)         // 64 x MROW(272) = 17408 (fp16 D staging)
#define EDGE_SMEM (E_MSG + 17408)      // 100352 -> 2 CTAs/SM

__global__ __launch_bounds__(256, 2) void edge_kernel(const float* __restrict__ edge_feat,
                                                      const int* __restrict__ senders,
                                                      const int* __restrict__ receivers) {
    extern __shared__ __align__(16) char smem[];
    uint32_t sb;
    asm("{ .reg .u64 t; cvta.to.shared.u64 t, %1; cvt.u32.u64 %0, t; }" : "=r"(sb) : "l"(smem));
    const int tid = threadIdx.x, wid = tid >> 5, lane = tid & 31;
    const int g = lane >> 2, t4 = lane & 3, wm = wid >> 2, wn = wid & 3;

    // one-time: packed W1c into smem
    {
        const uint4* src = (const uint4*)&g_Bpack[0][0][0];  // 32768 B
        uint4* dst = (uint4*)(smem + E_B16);
#pragma unroll
        for (int i = tid; i < 2048; i += 256) dst[i] = src[i];
    }

    // ldmatrix lane addressing: matrix j from lanes 8j..8j+7
    const int lrow = lane & 7, lsel = lane >> 3;
    const uint32_t a_lane_off =
        (uint32_t)(((lsel & 1) * 8 + lrow) * AROW + (lsel >> 1) * 16);
    const uint32_t a_addr0 = sb + E_A16 + (wm * 32 + 0) * AROW + a_lane_off;
    const uint32_t a_addr1 = sb + E_A16 + (wm * 32 + 16) * AROW + a_lane_off;

    // prefetch: raw tile is 64 rows x 512 B, fully contiguous -> linear copy
    auto prefetch = [&](int t) {
        if (t < N_TILES) {
            const char* src = (const char*)(edge_feat + (size_t)t * TILE_M * H);
#pragma unroll
            for (int j = 0; j < 8; j++) {
                int i = tid + j * 256;
                cp16(sb + E_RAW + i * 16, src + (size_t)i * 16);
            }
        }
        CP_COMMIT();
    };

    prefetch(blockIdx.x);

    for (int t = blockIdx.x; t < N_TILES; t += EDGE_GRID) {
        CP_WAIT0();
        __syncthreads();   // RAW ready; all threads past previous epilogue

        // ---- convert RAW fp32 -> A16 fp16: 64 rows x 32 float4/row = 2048 float4 ----
#pragma unroll
        for (int j = 0; j < 8; j++) {
            int i = tid + j * 256;
            int row = i >> 5, c4 = i & 31;
            float4 v = *(const float4*)(smem + E_RAW + (size_t)i * 16);
            *(uint2*)(smem + E_A16 + row * AROW + c4 * 8) =
                make_uint2(packh2(v.x, v.y), packh2(v.z, v.w));
        }
        __syncthreads();   // A16 ready; RAW fully consumed

        prefetch(t + EDGE_GRID);   // overwrites RAW; hidden under GEMM + epilogue

        // ---- GEMM: ldmatrix A, frag-major B, single fp16 pass ----
        float acc[2][4][4];
#pragma unroll
        for (int mt = 0; mt < 2; mt++)
#pragma unroll
            for (int nt = 0; nt < 4; nt++)
#pragma unroll
                for (int q = 0; q < 4; q++) acc[mt][nt][q] = 0.f;

        const uint2* B16 = (const uint2*)(smem + E_B16);
#pragma unroll
        for (int ks = 0; ks < 8; ks++) {
            uint32_t a0[4], a1[4];
            LDSM4(a0, a_addr0 + ks * 32);
            LDSM4(a1, a_addr1 + ks * 32);
#pragma unroll
            for (int nt = 0; nt < 4; nt++) {
                int n = wn * 32 + nt * 8 + g;
                uint2 b = B16[(ks * 128 + n) * 4 + t4];
                mma16816(acc[0][nt], a0, b.x, b.y);
                mma16816(acc[1][nt], a1, b.x, b.y);
            }
        }

        // ---- stage D to MSG (fp16, conflict-free STS.32) ----
#pragma unroll
        for (int mt = 0; mt < 2; mt++)
#pragma unroll
            for (int nt = 0; nt < 4; nt++)
#pragma unroll
                for (int rh = 0; rh < 2; rh++) {
                    int row = wm * 32 + mt * 16 + rh * 8 + g;
                    int c = wn * 32 + nt * 8 + t4 * 2;
                    *(uint32_t*)(smem + E_MSG + row * MROW + c * 2) =
                        packh2(acc[mt][nt][rh * 2 + 0], acc[mt][nt][rh * 2 + 1]);
                }
        __syncthreads();   // MSG complete

        // ---- epilogue: warp-per-edge, coalesced fp16 gathers + RED.128 ----
        const size_t e0 = (size_t)t * TILE_M;
#pragma unroll
        for (int j = 0; j < 8; j++) {
            int row = wid * 8 + j;
            size_t e = e0 + row;
            int s = __ldg(senders + e);
            int r = __ldg(receivers + e);
            uint2 mm = *(const uint2*)(smem + E_MSG + row * MROW + lane * 8);
            float2 f0 = __half22float2(*(__half2*)&mm.x);
            float2 f1 = __half22float2(*(__half2*)&mm.y);
            uint2 psu = __ldg((const uint2*)(g_Ph + (size_t)s * 256) + lane);
            uint2 pru = __ldg((const uint2*)(g_Ph + (size_t)r * 256 + 128) + lane);
            float2 ps0 = __half22float2(*(__half2*)&psu.x);
            float2 ps1 = __half22float2(*(__half2*)&psu.y);
            float2 pr0 = __half22float2(*(__half2*)&pru.x);
            float2 pr1 = __half22float2(*(__half2*)&pru.y);
            float v0 = fmaxf(f0.x + ps0.x + pr0.x, 0.f);
            float v1 = fmaxf(f0.y + ps0.y + pr0.y, 0.f);
            float v2 = fmaxf(f1.x + ps1.x + pr1.x, 0.f);
            float v3 = fmaxf(f1.y + ps1.y + pr1.y, 0.f);
            asm volatile("red.global.add.v4.f32 [%0], {%1,%2,%3,%4};"
                         :: "l"(g_accum + (size_t)r * H + lane * 4),
                            "f"(v0), "f"(v1), "f"(v2), "f"(v3) : "memory");
        }
    }
}

// ---------------- K3: layernorm ----------------
__global__ __launch_bounds__(256) void ln_kernel(const float* __restrict__ gamma,
                                                 const float* __restrict__ beta,
                                                 float* __restrict__ out) {
    const int wid = threadIdx.x >> 5, lid = threadIdx.x & 31;
    const int n = blockIdx.x * 8 + wid;
    if (n >= N_NODES) return;
    float4 v = ((const float4*)(g_accum + (size_t)n * H))[lid];
    float s = v.x + v.y + v.z + v.w;
#pragma unroll
    for (int o = 16; o > 0; o >>= 1) s += __shfl_xor_sync(0xFFFFFFFFu, s, o);
    float mu = s * (1.0f / H);
    float dx = v.x - mu, dy = v.y - mu, dz = v.z - mu, dw = v.w - mu;
    float ss = dx * dx + dy * dy + dz * dz + dw * dw;
#pragma unroll
    for (int o = 16; o > 0; o >>= 1) ss += __shfl_xor_sync(0xFFFFFFFFu, ss, o);
    float rs = rsqrtf(ss * (1.0f / H) + LN_EPS);
    float4 gm = ((const float4*)gamma)[lid];
    float4 b = ((const float4*)beta)[lid];
    float4 o4 = make_float4(gm.x * dx * rs + b.x, gm.y * dy * rs + b.y,
                            gm.z * dz * rs + b.z, gm.w * dw * rs + b.w);
    ((float4*)(out + (size_t)n * H))[lid] = o4;
}

// ---------------- launch ----------------
extern "C" void kernel_launch(void* const* d_in, const int* in_sizes, int n_in,
                              void* d_out, int out_size) {
    const float* x         = (const float*)d_in[0];
    const int*   senders   = (const int*)d_in[1];
    const int*   receivers = (const int*)d_in[2];
    const float* edge_feat = (const float*)d_in[3];
    const float* W1        = (const float*)d_in[4];
    const float* b1        = (const float*)d_in[5];
    const float* gamma     = (const float*)d_in[6];
    const float* beta      = (const float*)d_in[7];
    float* out = (float*)d_out;

    cudaFuncSetAttribute(node_proj_kernel, cudaFuncAttributeMaxDynamicSharedMemorySize, NODE_SMEM);
    cudaFuncSetAttribute(edge_kernel, cudaFuncAttributeMaxDynamicSharedMemorySize, EDGE_SMEM);

    splitw_kernel<<<128, 256>>>(W1);
    packw_kernel<<<16, 256>>>(W1);
    node_proj_kernel<<<dim3((N_NODES + 127) / 128, 2), 256, NODE_SMEM>>>(x, b1);
    edge_kernel<<<EDGE_GRID, 256, EDGE_SMEM>>>(edge_feat, senders, receivers);
    ln_kernel<<<(N_NODES + 7) / 8, 256>>>(gamma, beta, out);
}